// round 6
// baseline (speedup 1.0000x reference)
#include <cuda_runtime.h>
#include <cuda_fp16.h>
#include <math.h>
#include <stdint.h>

// ---------------- problem dims ----------------
#define BB 4
#define TT 2048
#define DD 1024
#define VV 32000
#define NTOK (BB * TT)                 // 8192
#define NLOGITS 262144000LL
#define ATT_ELEMS ((long long)BB * TT * TT)
#define LM_NTILES (VV / 256)           // 125 (BN=256 LM tiles)

// ---------------- GEMM tiling ----------------
#define BM 128
#define BKC 64
#define GROUP_M 8
#define GEMM_THREADS 256

// ---------------- scratch ----------------
__device__ __half g_h_hi[NTOK * DD],  g_h_lo[NTOK * DD];
__device__ __half g_q_hi[NTOK * DD],  g_q_lo[NTOK * DD];
__device__ __half g_k_hi[NTOK * DD],  g_k_lo[NTOK * DD];
__device__ float  g_v[NTOK * DD];
__device__ __half g_vT_hi[NTOK * DD], g_vT_lo[NTOK * DD];
__device__ float  g_att[ATT_ELEMS];
__device__ __half g_att_hi[ATT_ELEMS], g_att_lo[ATT_ELEMS];
__device__ __half g_y_hi[NTOK * DD];
__device__ __half g_WqT_hi[DD * DD],  g_WqT_lo[DD * DD];
__device__ __half g_WkT_hi[DD * DD],  g_WkT_lo[DD * DD];
__device__ __half g_WvT_hi[DD * DD],  g_WvT_lo[DD * DD];
__device__ __half g_WlmT_hi[(long long)VV * DD];
__device__ float  g_pm[(long long)NTOK * LM_NTILES];
__device__ float  g_ps[(long long)NTOK * LM_NTILES];
__device__ float  g_rowloss[NTOK];

// ---------------- helpers ----------------
__device__ __forceinline__ uint32_t smem_u32(const void* p) {
    uint32_t a;
    asm("{ .reg .u64 t; cvta.to.shared.u64 t, %1; cvt.u32.u64 %0, t; }" : "=r"(a) : "l"(p));
    return a;
}
__device__ __forceinline__ void cp16(uint32_t dst, const void* src) {
    asm volatile("cp.async.cg.shared.global [%0], [%1], 16;" :: "r"(dst), "l"(src));
}
__device__ __forceinline__ void ldsm_x4(uint32_t* r, uint32_t addr) {
    asm volatile("ldmatrix.sync.aligned.m8n8.x4.shared.b16 {%0,%1,%2,%3}, [%4];"
                 : "=r"(r[0]), "=r"(r[1]), "=r"(r[2]), "=r"(r[3]) : "r"(addr));
}
__device__ __forceinline__ void ldsm_x2(uint32_t* r, uint32_t addr) {
    asm volatile("ldmatrix.sync.aligned.m8n8.x2.shared.b16 {%0,%1}, [%2];"
                 : "=r"(r[0]), "=r"(r[1]) : "r"(addr));
}
__device__ __forceinline__ void mma_fp16(float* c, const uint32_t* a, const uint32_t* b) {
    asm volatile("mma.sync.aligned.m16n8k16.row.col.f32.f16.f16.f32 "
                 "{%0,%1,%2,%3}, {%4,%5,%6,%7}, {%8,%9}, {%0,%1,%2,%3};"
                 : "+f"(c[0]), "+f"(c[1]), "+f"(c[2]), "+f"(c[3])
                 : "r"(a[0]), "r"(a[1]), "r"(a[2]), "r"(a[3]), "r"(b[0]), "r"(b[1]));
}
__device__ __forceinline__ void split_h(float x, __half& hi, __half& lo) {
    hi = __float2half_rn(x);
    lo = __float2half_rn(x - __half2float(hi));
}

// ---------------- split-fp16 HMMA GEMM ----------------
// MODE 0: normal. MODE 1: lower-triangular tiles. MODE 2: K truncated at m0+BM.
// NPASS 3: hh + h*Blo + Alo*h.  NPASS 2: hh + h*Blo.  NPASS 1: hh.
// OUTM 0: f32. OUTM 1: fp16 hi. OUTM 2: fp16 hi+lo.
// FUSE: per-tile row (max, sumexp) partials. BNT: tile N (128 or 256).
template <int MODE, int NPASS, int OUTM, bool FUSE, int BNT>
__global__ void __launch_bounds__(GEMM_THREADS)
mmagemm(const __half* __restrict__ Ahi, const __half* __restrict__ Alo,
        const __half* __restrict__ Bhi, const __half* __restrict__ Blo,
        const float* __restrict__ bias, float alpha,
        float* __restrict__ C, __half* __restrict__ Chi, __half* __restrict__ Clo,
        float* __restrict__ pm, float* __restrict__ ps,
        int M, int N, int K,
        long long sA, long long sB, long long sC) {
    constexpr int NT = BNT / 32;                 // n-subtiles per warp
    constexpr int ATILE = 16384;
    constexpr int BTILE = BNT * 128;
    constexpr int NAt = (NPASS == 3) ? 2 : 1;
    constexpr int NBt = (NPASS >= 2) ? 2 : 1;
    constexpr int T_AHI = 0;
    constexpr int T_ALO = ATILE;
    constexpr int T_BHI = NAt * ATILE;
    constexpr int T_BLO = T_BHI + BTILE;
    constexpr int STAGE = NAt * ATILE + NBt * BTILE;

    extern __shared__ char smem[];
    const uint32_t sb = smem_u32(smem);
    const int tid = threadIdx.x;
    const int wid = tid >> 5, lane = tid & 31;
    const int wm = wid >> 2, wn = wid & 3;

    Ahi += blockIdx.z * sA;  if (NPASS == 3) Alo += blockIdx.z * sA;
    Bhi += blockIdx.z * sB;  if (NPASS >= 2) Blo += blockIdx.z * sB;
    if (OUTM == 0) C += blockIdx.z * sC;
    else { Chi += blockIdx.z * sC; if (OUTM == 2) Clo += blockIdx.z * sC; }

    int m0, n0;
    if (MODE == 1) {
        int idx = blockIdx.x;
        int row = (int)((sqrtf(8.0f * idx + 1.0f) - 1.0f) * 0.5f);
        while ((row + 1) * (row + 2) / 2 <= idx) ++row;
        while (row * (row + 1) / 2 > idx) --row;
        int col = idx - row * (row + 1) / 2;
        m0 = row * BM; n0 = col * BNT;
    } else {
        const int npn = N / BNT, npm = M / BM;
        int pid = blockIdx.x;
        int group = GROUP_M * npn;
        int gid = pid / group;
        int first = gid * GROUP_M;
        int gsz = min(GROUP_M, npm - first);
        m0 = (first + (pid % gsz)) * BM;
        n0 = ((pid % group) / gsz) * BNT;
    }

    int NC = K / BKC;
    if (MODE == 2) NC = min(NC, (m0 + BM) / BKC);

    auto load_stage = [&](int chunk, int stage) {
        const uint32_t st = sb + stage * STAGE;
        const int kk = chunk * BKC;
#pragma unroll
        for (int it = 0; it < 4; it++) {
            int idx = tid + it * 256;
            int row = idx >> 3, ch = idx & 7;
            uint32_t dst = st + (uint32_t)(row * 128 + ((ch ^ (row & 7)) * 16));
            long long ga = (long long)(m0 + row) * K + kk + ch * 8;
            cp16(dst + T_AHI, Ahi + ga);
            if (NPASS == 3) cp16(dst + T_ALO, Alo + ga);
        }
#pragma unroll
        for (int it = 0; it < BNT / 32; it++) {
            int idx = tid + it * 256;
            int row = idx >> 3, ch = idx & 7;
            uint32_t dst = st + (uint32_t)(row * 128 + ((ch ^ (row & 7)) * 16));
            long long gb = (long long)(n0 + row) * K + kk + ch * 8;
            cp16(dst + T_BHI, Bhi + gb);
            if (NPASS >= 2) cp16(dst + T_BLO, Blo + gb);
        }
        asm volatile("cp.async.commit_group;" ::: "memory");
    };

    float acc[4][NT][4];
#pragma unroll
    for (int a = 0; a < 4; a++)
#pragma unroll
        for (int b = 0; b < NT; b++)
#pragma unroll
            for (int c = 0; c < 4; c++) acc[a][b][c] = 0.0f;

    load_stage(0, 0);
    load_stage(1, 1);

    for (int i = 0; i < NC; i++) {
        if (i + 1 < NC) asm volatile("cp.async.wait_group 1;" ::: "memory");
        else            asm volatile("cp.async.wait_group 0;" ::: "memory");
        __syncthreads();

        const uint32_t st = sb + (i % 3) * STAGE;
#pragma unroll
        for (int ks = 0; ks < 4; ks++) {
            uint32_t ah[4][4], al[4][4], bh[NT][2], bl[NT][2];
#pragma unroll
            for (int mt = 0; mt < 4; mt++) {
                int row = wm * 64 + mt * 16 + (lane & 15);
                uint32_t off = (uint32_t)(row * 128 + ks * 32 + ((lane >> 4) * 16));
                off = off ^ ((off >> 3) & 0x70);
                ldsm_x4(ah[mt], st + T_AHI + off);
                if (NPASS == 3) ldsm_x4(al[mt], st + T_ALO + off);
            }
#pragma unroll
            for (int nt = 0; nt < NT; nt++) {
                int row = wn * (BNT / 4) + nt * 8 + (lane & 7);
                uint32_t off = (uint32_t)(row * 128 + ks * 32 + (((lane >> 3) & 1) * 16));
                off = off ^ ((off >> 3) & 0x70);
                ldsm_x2(bh[nt], st + T_BHI + off);
                if (NPASS >= 2) ldsm_x2(bl[nt], st + T_BLO + off);
            }
#pragma unroll
            for (int mt = 0; mt < 4; mt++)
#pragma unroll
                for (int nt = 0; nt < NT; nt++) {
                    mma_fp16(acc[mt][nt], ah[mt], bh[nt]);
                    if (NPASS >= 2) mma_fp16(acc[mt][nt], ah[mt], bl[nt]);
                    if (NPASS == 3) mma_fp16(acc[mt][nt], al[mt], bh[nt]);
                }
        }
        __syncthreads();
        if (i + 2 < NC) load_stage(i + 2, (i + 2) % 3);
    }

    // finalize values (alpha, bias)
    const int tg = lane >> 2;
    const int tc = (lane & 3) * 2;
#pragma unroll
    for (int mt = 0; mt < 4; mt++)
#pragma unroll
        for (int nt = 0; nt < NT; nt++) {
            int c0 = n0 + wn * (BNT / 4) + nt * 8 + tc;
            float b0 = bias ? bias[c0] : 0.0f;
            float b1 = bias ? bias[c0 + 1] : 0.0f;
            acc[mt][nt][0] = alpha * acc[mt][nt][0] + b0;
            acc[mt][nt][1] = alpha * acc[mt][nt][1] + b1;
            acc[mt][nt][2] = alpha * acc[mt][nt][2] + b0;
            acc[mt][nt][3] = alpha * acc[mt][nt][3] + b1;
        }

    // stores
#pragma unroll
    for (int mt = 0; mt < 4; mt++)
#pragma unroll
        for (int nt = 0; nt < NT; nt++) {
            int r0 = m0 + wm * 64 + mt * 16 + tg;
            int c0 = n0 + wn * (BNT / 4) + nt * 8 + tc;
            if (OUTM == 0) {
                *(float2*)(C + (long long)r0 * N + c0) = make_float2(acc[mt][nt][0], acc[mt][nt][1]);
                *(float2*)(C + (long long)(r0 + 8) * N + c0) = make_float2(acc[mt][nt][2], acc[mt][nt][3]);
            } else if (OUTM == 1) {
                *(__half2*)(Chi + (long long)r0 * N + c0) =
                    __half2(__float2half_rn(acc[mt][nt][0]), __float2half_rn(acc[mt][nt][1]));
                *(__half2*)(Chi + (long long)(r0 + 8) * N + c0) =
                    __half2(__float2half_rn(acc[mt][nt][2]), __float2half_rn(acc[mt][nt][3]));
            } else {
                __half h0, l0, h1, l1;
                split_h(acc[mt][nt][0], h0, l0); split_h(acc[mt][nt][1], h1, l1);
                *(__half2*)(Chi + (long long)r0 * N + c0) = __half2(h0, h1);
                *(__half2*)(Clo + (long long)r0 * N + c0) = __half2(l0, l1);
                split_h(acc[mt][nt][2], h0, l0); split_h(acc[mt][nt][3], h1, l1);
                *(__half2*)(Chi + (long long)(r0 + 8) * N + c0) = __half2(h0, h1);
                *(__half2*)(Clo + (long long)(r0 + 8) * N + c0) = __half2(l0, l1);
            }
        }

    // fused per-tile row logsumexp partials
    if (FUSE) {
        float* smM = (float*)smem;            // [4][128]
        float* smS = smM + 512;
        float rm[8], rs[8];
#pragma unroll
        for (int mt = 0; mt < 4; mt++)
#pragma unroll
            for (int hf = 0; hf < 2; hf++) {
                float m = -INFINITY;
#pragma unroll
                for (int nt = 0; nt < NT; nt++) {
                    m = fmaxf(m, acc[mt][nt][hf * 2 + 0]);
                    m = fmaxf(m, acc[mt][nt][hf * 2 + 1]);
                }
                rm[mt * 2 + hf] = m;
            }
#pragma unroll
        for (int s = 0; s < 8; s++) {
            rm[s] = fmaxf(rm[s], __shfl_xor_sync(0xffffffffu, rm[s], 1));
            rm[s] = fmaxf(rm[s], __shfl_xor_sync(0xffffffffu, rm[s], 2));
        }
#pragma unroll
        for (int mt = 0; mt < 4; mt++)
#pragma unroll
            for (int hf = 0; hf < 2; hf++) {
                float m = rm[mt * 2 + hf], s = 0.0f;
#pragma unroll
                for (int nt = 0; nt < NT; nt++) {
                    s += __expf(acc[mt][nt][hf * 2 + 0] - m);
                    s += __expf(acc[mt][nt][hf * 2 + 1] - m);
                }
                rs[mt * 2 + hf] = s;
            }
#pragma unroll
        for (int s = 0; s < 8; s++) {
            rs[s] += __shfl_xor_sync(0xffffffffu, rs[s], 1);
            rs[s] += __shfl_xor_sync(0xffffffffu, rs[s], 2);
        }
        if ((lane & 3) == 0) {
#pragma unroll
            for (int mt = 0; mt < 4; mt++)
#pragma unroll
                for (int hf = 0; hf < 2; hf++) {
                    int rin = wm * 64 + mt * 16 + hf * 8 + tg;
                    smM[wn * 128 + rin] = rm[mt * 2 + hf];
                    smS[wn * 128 + rin] = rs[mt * 2 + hf];
                }
        }
        __syncthreads();
        if (tid < 128) {
            float M4 = smM[tid];
            M4 = fmaxf(M4, smM[128 + tid]);
            M4 = fmaxf(M4, smM[256 + tid]);
            M4 = fmaxf(M4, smM[384 + tid]);
            float S4 = smS[tid] * __expf(smM[tid] - M4)
                     + smS[128 + tid] * __expf(smM[128 + tid] - M4)
                     + smS[256 + tid] * __expf(smM[256 + tid] - M4)
                     + smS[384 + tid] * __expf(smM[384 + tid] - M4);
            long long o = (long long)(m0 + tid) * (N / BNT) + n0 / BNT;
            pm[o] = M4; ps[o] = S4;
        }
    }
}

// ---------------- embedding (split fp16) ----------------
__global__ void embed_split_kernel(const int* __restrict__ x,
                                   const float* __restrict__ tok,
                                   const float* __restrict__ pos,
                                   __half* __restrict__ hhi, __half* __restrict__ hlo) {
    int i = blockIdx.x * blockDim.x + threadIdx.x;
    if (i >= NTOK * DD) return;
    int row = i >> 10;
    int d = i & 1023;
    int t = row & (TT - 1);
    float v = tok[(long long)x[row] * DD + d] + pos[t * DD + d];
    __half hi, lo;
    split_h(v, hi, lo);
    hhi[i] = hi; hlo[i] = lo;
}

// ---------------- transpose + split (lo optional) ----------------
__global__ void transpose_split_kernel(const float* __restrict__ in,
                                       __half* __restrict__ ohi, __half* __restrict__ olo,
                                       int R, int C, long long sIn, long long sOut) {
    __shared__ float tbuf[32][33];
    in += blockIdx.z * sIn;
    ohi += blockIdx.z * sOut;
    if (olo) olo += blockIdx.z * sOut;
    int c0 = blockIdx.x * 32, r0 = blockIdx.y * 32;
    int tx = threadIdx.x, ty = threadIdx.y;
#pragma unroll
    for (int i = 0; i < 32; i += 8)
        tbuf[ty + i][tx] = in[(long long)(r0 + ty + i) * C + c0 + tx];
    __syncthreads();
#pragma unroll
    for (int i = 0; i < 32; i += 8) {
        float v = tbuf[tx][ty + i];
        long long o = (long long)(c0 + ty + i) * R + r0 + tx;
        if (olo) {
            __half hi, lo;
            split_h(v, hi, lo);
            ohi[o] = hi; olo[o] = lo;
        } else {
            ohi[o] = __float2half_rn(v);
        }
    }
}

// ---------------- reductions ----------------
__device__ __forceinline__ float blockMax(float v, float* red) {
#pragma unroll
    for (int o = 16; o; o >>= 1) v = fmaxf(v, __shfl_xor_sync(0xffffffffu, v, o));
    if ((threadIdx.x & 31) == 0) red[threadIdx.x >> 5] = v;
    __syncthreads();
    float r = red[0];
#pragma unroll
    for (int i = 1; i < 8; i++) r = fmaxf(r, red[i]);
    __syncthreads();
    return r;
}
__device__ __forceinline__ float blockSum(float v, float* red) {
#pragma unroll
    for (int o = 16; o; o >>= 1) v += __shfl_xor_sync(0xffffffffu, v, o);
    if ((threadIdx.x & 31) == 0) red[threadIdx.x >> 5] = v;
    __syncthreads();
    float r = red[0];
#pragma unroll
    for (int i = 1; i < 8; i++) r += red[i];
    __syncthreads();
    return r;
}

// ---------------- causal softmax -> split fp16 ----------------
__global__ void __launch_bounds__(256)
softmax_split_kernel(const float* __restrict__ att,
                     __half* __restrict__ ahi, __half* __restrict__ alo) {
    __shared__ float red[8];
    int row = blockIdx.x;
    int i = row & (TT - 1);
    const float* p = att + (long long)row * TT;
    __half* ph = ahi + (long long)row * TT;
    __half* pl = alo + (long long)row * TT;
    int tid = threadIdx.x;

    float m = -INFINITY;
    for (int j = tid; j <= i; j += 256) m = fmaxf(m, p[j]);
    m = blockMax(m, red);

    float s = 0.0f;
    for (int j = tid; j <= i; j += 256) s += expf(p[j] - m);
    s = blockSum(s, red);
    float inv = 1.0f / s;

    for (int j = tid; j <= i; j += 256) {
        float e = expf(p[j] - m) * inv;
        __half hi, lo;
        split_h(e, hi, lo);
        ph[j] = hi; pl[j] = lo;
    }
    // only zero up to the K-truncation boundary of the attn@v GEMM
    int jend = ((i >> 7) + 1) << 7;
    __half z = __float2half(0.0f);
    for (int j = i + 1 + tid; j < jend; j += 256) { ph[j] = z; pl[j] = z; }
}

// ---------------- rowloss from fused partials ----------------
__global__ void __launch_bounds__(32)
rowloss_partials_kernel(const float* __restrict__ pm, const float* __restrict__ ps,
                        const float* __restrict__ logits, const int* __restrict__ target,
                        float* __restrict__ rowloss) {
    int row = blockIdx.x;
    int lane = threadIdx.x;
    float m = -INFINITY, s = 0.0f;
    for (int t = lane; t < LM_NTILES; t += 32) {
        long long o = (long long)row * LM_NTILES + t;
        float tm = pm[o], ts = ps[o];
        float nm = fmaxf(m, tm);
        s = s * __expf(m - nm) + ts * __expf(tm - nm);
        m = nm;
    }
#pragma unroll
    for (int o = 16; o; o >>= 1) {
        float om = __shfl_xor_sync(0xffffffffu, m, o);
        float os = __shfl_xor_sync(0xffffffffu, s, o);
        float nm = fmaxf(m, om);
        s = s * __expf(m - nm) + os * __expf(om - nm);
        m = nm;
    }
    if (lane == 0)
        rowloss[row] = m + logf(s) - logits[(long long)row * VV + target[row]];
}

__global__ void __launch_bounds__(256)
loss_reduce_kernel(const float* __restrict__ rowloss, float* __restrict__ out) {
    __shared__ float red[8];
    float s = 0.0f;
    for (int r = threadIdx.x; r < NTOK; r += 256) s += rowloss[r];
    s = blockSum(s, red);
    if (threadIdx.x == 0) out[0] = s / (float)NTOK;
}

// ---------------- launch ----------------
extern "C" void kernel_launch(void* const* d_in, const int* in_sizes, int n_in,
                              void* d_out, int out_size) {
    const int*   x      = (const int*)d_in[0];
    const int*   target = (const int*)d_in[1];
    const float* tok    = (const float*)d_in[2];
    const float* pos    = (const float*)d_in[3];
    const float* Wq     = (const float*)d_in[4];
    const float* bq     = (const float*)d_in[5];
    const float* Wk     = (const float*)d_in[6];
    const float* bk     = (const float*)d_in[7];
    const float* Wv     = (const float*)d_in[8];
    const float* bv     = (const float*)d_in[9];
    const float* W_lm   = (const float*)d_in[10];
    const float* b_lm   = (const float*)d_in[11];
    float* out = (float*)d_out;

    const int SM3_128 = 3 * 4 * 16384;        // 196608  (3-pass, BN=128)
    const int SM2_128 = 3 * 3 * 16384;        // 147456  (2-pass, BN=128)
    const int SM1_256 = 3 * (16384 + 32768);  // 147456  (1-pass, BN=256)

    cudaFuncSetAttribute((const void*)mmagemm<0,3,2,false,128>, cudaFuncAttributeMaxDynamicSharedMemorySize, SM3_128);
    cudaFuncSetAttribute((const void*)mmagemm<0,2,0,false,128>, cudaFuncAttributeMaxDynamicSharedMemorySize, SM2_128);
    cudaFuncSetAttribute((const void*)mmagemm<1,3,0,false,128>, cudaFuncAttributeMaxDynamicSharedMemorySize, SM3_128);
    cudaFuncSetAttribute((const void*)mmagemm<2,3,1,false,128>, cudaFuncAttributeMaxDynamicSharedMemorySize, SM3_128);
    cudaFuncSetAttribute((const void*)mmagemm<0,1,0,true,256>,  cudaFuncAttributeMaxDynamicSharedMemorySize, SM1_256);

    __half *h_hi, *h_lo, *q_hi, *q_lo, *k_hi, *k_lo, *vT_hi, *vT_lo;
    __half *att_hi, *att_lo, *y_hi;
    __half *WqT_hi, *WqT_lo, *WkT_hi, *WkT_lo, *WvT_hi, *WvT_lo, *WlmT_hi;
    float *v, *att, *rowloss, *pm, *ps;
    cudaGetSymbolAddress((void**)&h_hi, g_h_hi);   cudaGetSymbolAddress((void**)&h_lo, g_h_lo);
    cudaGetSymbolAddress((void**)&q_hi, g_q_hi);   cudaGetSymbolAddress((void**)&q_lo, g_q_lo);
    cudaGetSymbolAddress((void**)&k_hi, g_k_hi);   cudaGetSymbolAddress((void**)&k_lo, g_k_lo);
    cudaGetSymbolAddress((void**)&v, g_v);
    cudaGetSymbolAddress((void**)&vT_hi, g_vT_hi); cudaGetSymbolAddress((void**)&vT_lo, g_vT_lo);
    cudaGetSymbolAddress((void**)&att, g_att);
    cudaGetSymbolAddress((void**)&att_hi, g_att_hi); cudaGetSymbolAddress((void**)&att_lo, g_att_lo);
    cudaGetSymbolAddress((void**)&y_hi, g_y_hi);
    cudaGetSymbolAddress((void**)&WqT_hi, g_WqT_hi); cudaGetSymbolAddress((void**)&WqT_lo, g_WqT_lo);
    cudaGetSymbolAddress((void**)&WkT_hi, g_WkT_hi); cudaGetSymbolAddress((void**)&WkT_lo, g_WkT_lo);
    cudaGetSymbolAddress((void**)&WvT_hi, g_WvT_hi); cudaGetSymbolAddress((void**)&WvT_lo, g_WvT_lo);
    cudaGetSymbolAddress((void**)&WlmT_hi, g_WlmT_hi);
    cudaGetSymbolAddress((void**)&pm, g_pm);       cudaGetSymbolAddress((void**)&ps, g_ps);
    cudaGetSymbolAddress((void**)&rowloss, g_rowloss);

    dim3 tb(32, 8);

    embed_split_kernel<<<(NTOK * DD + 255) / 256, 256>>>(x, tok, pos, h_hi, h_lo);

    transpose_split_kernel<<<dim3(DD / 32, DD / 32, 1), tb>>>(Wq, WqT_hi, WqT_lo, DD, DD, 0, 0);
    transpose_split_kernel<<<dim3(DD / 32, DD / 32, 1), tb>>>(Wk, WkT_hi, WkT_lo, DD, DD, 0, 0);
    transpose_split_kernel<<<dim3(DD / 32, DD / 32, 1), tb>>>(Wv, WvT_hi, WvT_lo, DD, DD, 0, 0);
    transpose_split_kernel<<<dim3(VV / 32, DD / 32, 1), tb>>>(W_lm, WlmT_hi, nullptr, DD, VV, 0, 0);

    // q, k: 3-pass split-out; v: 2-pass fp32-out
    {
        dim3 grid((NTOK / BM) * (DD / 128), 1, 1);
        mmagemm<0,3,2,false,128><<<grid, GEMM_THREADS, SM3_128>>>(h_hi, h_lo, WqT_hi, WqT_lo, bq, 1.0f,
            nullptr, q_hi, q_lo, nullptr, nullptr, NTOK, DD, DD, 0, 0, 0);
        mmagemm<0,3,2,false,128><<<grid, GEMM_THREADS, SM3_128>>>(h_hi, h_lo, WkT_hi, WkT_lo, bk, 1.0f,
            nullptr, k_hi, k_lo, nullptr, nullptr, NTOK, DD, DD, 0, 0, 0);
        mmagemm<0,2,0,false,128><<<grid, GEMM_THREADS, SM2_128>>>(h_hi, nullptr, WvT_hi, WvT_lo, bv, 1.0f,
            v, nullptr, nullptr, nullptr, nullptr, NTOK, DD, DD, 0, 0, 0);
    }

    transpose_split_kernel<<<dim3(DD / 32, TT / 32, BB), tb>>>(v, vT_hi, vT_lo, TT, DD,
        (long long)TT * DD, (long long)TT * DD);

    // scores: 3-pass, lower-triangular tiles only
    {
        dim3 grid(136, 1, BB);
        mmagemm<1,3,0,false,128><<<grid, GEMM_THREADS, SM3_128>>>(q_hi, q_lo, k_hi, k_lo, nullptr, 0.03125f,
            att, nullptr, nullptr, nullptr, nullptr, TT, TT, DD,
            (long long)TT * DD, (long long)TT * DD, (long long)TT * TT);
    }

    softmax_split_kernel<<<NTOK, 256>>>(att, att_hi, att_lo);

    // y = attn @ v: 3-pass, K truncated, hi-only output
    {
        dim3 grid((TT / BM) * (DD / 128), 1, BB);
        mmagemm<2,3,1,false,128><<<grid, GEMM_THREADS, SM3_128>>>(att_hi, att_lo, vT_hi, vT_lo, nullptr, 1.0f,
            nullptr, y_hi, nullptr, nullptr, nullptr, TT, DD, TT,
            (long long)TT * TT, (long long)TT * DD, (long long)TT * DD);
    }

    // logits: 1-pass fp16, BN=256 tile + fused loss partials
    {
        dim3 grid((NTOK / BM) * (VV / 256), 1, 1);
        mmagemm<0,1,0,true,256><<<grid, GEMM_THREADS, SM1_256>>>(y_hi, nullptr, WlmT_hi, nullptr, b_lm, 1.0f,
            out, nullptr, nullptr, pm, ps, NTOK, VV, DD, 0, 0, 0);
    }

    rowloss_partials_kernel<<<NTOK, 32>>>(pm, ps, out, target, rowloss);
    if ((long long)out_size > NLOGITS) {
        loss_reduce_kernel<<<1, 256>>>(rowloss, out + NLOGITS);
    }
}

// round 7
// speedup vs baseline: 1.0215x; 1.0215x over previous
#include <cuda_runtime.h>
#include <cuda_fp16.h>
#include <math.h>
#include <stdint.h>

// ---------------- problem dims ----------------
#define BB 4
#define TT 2048
#define DD 1024
#define VV 32000
#define NTOK (BB * TT)                 // 8192
#define NLOGITS 262144000LL
#define ATT_ELEMS ((long long)BB * TT * TT)
#define LM_NTILES (VV / 128)           // 250

// ---------------- GEMM tiling ----------------
#define BM 128
#define BKC 64
#define GROUP_M 8
#define GEMM_THREADS 256

// ---------------- scratch ----------------
__device__ __half g_h_hi[NTOK * DD],  g_h_lo[NTOK * DD];
__device__ __half g_q_hi[NTOK * DD],  g_q_lo[NTOK * DD];
__device__ __half g_k_hi[NTOK * DD],  g_k_lo[NTOK * DD];
__device__ float  g_v[NTOK * DD];
__device__ __half g_vT_hi[NTOK * DD], g_vT_lo[NTOK * DD];
__device__ float  g_att[ATT_ELEMS];
__device__ __half g_att_hi[ATT_ELEMS], g_att_lo[ATT_ELEMS];
__device__ __half g_y_hi[NTOK * DD];
__device__ __half g_WqT_hi[DD * DD],  g_WqT_lo[DD * DD];
__device__ __half g_WkT_hi[DD * DD],  g_WkT_lo[DD * DD];
__device__ __half g_WvT_hi[DD * DD],  g_WvT_lo[DD * DD];
__device__ __half g_WlmT_hi[(long long)VV * DD];
__device__ float  g_pm[(long long)NTOK * LM_NTILES];
__device__ float  g_ps[(long long)NTOK * LM_NTILES];
__device__ float  g_rowloss[NTOK];

// ---------------- helpers ----------------
__device__ __forceinline__ uint32_t smem_u32(const void* p) {
    uint32_t a;
    asm("{ .reg .u64 t; cvta.to.shared.u64 t, %1; cvt.u32.u64 %0, t; }" : "=r"(a) : "l"(p));
    return a;
}
__device__ __forceinline__ void cp16(uint32_t dst, const void* src) {
    asm volatile("cp.async.cg.shared.global [%0], [%1], 16;" :: "r"(dst), "l"(src));
}
__device__ __forceinline__ void ldsm_x4(uint32_t* r, uint32_t addr) {
    asm volatile("ldmatrix.sync.aligned.m8n8.x4.shared.b16 {%0,%1,%2,%3}, [%4];"
                 : "=r"(r[0]), "=r"(r[1]), "=r"(r[2]), "=r"(r[3]) : "r"(addr));
}
__device__ __forceinline__ void ldsm_x2(uint32_t* r, uint32_t addr) {
    asm volatile("ldmatrix.sync.aligned.m8n8.x2.shared.b16 {%0,%1}, [%2];"
                 : "=r"(r[0]), "=r"(r[1]) : "r"(addr));
}
__device__ __forceinline__ void mma_fp16(float* c, const uint32_t* a, const uint32_t* b) {
    asm volatile("mma.sync.aligned.m16n8k16.row.col.f32.f16.f16.f32 "
                 "{%0,%1,%2,%3}, {%4,%5,%6,%7}, {%8,%9}, {%0,%1,%2,%3};"
                 : "+f"(c[0]), "+f"(c[1]), "+f"(c[2]), "+f"(c[3])
                 : "r"(a[0]), "r"(a[1]), "r"(a[2]), "r"(a[3]), "r"(b[0]), "r"(b[1]));
}
__device__ __forceinline__ void split_h(float x, __half& hi, __half& lo) {
    hi = __float2half_rn(x);
    lo = __float2half_rn(x - __half2float(hi));
}

// ---------------- split-fp16 HMMA GEMM (BN=128) ----------------
// MODE 0: normal. MODE 1: lower-triangular tiles. MODE 2: K truncated at m0+BM.
// NPASS 3: hh + h*Blo + Alo*h.  NPASS 2: hh + h*Blo.  NPASS 1: hh.
// OUTM 0: f32. OUTM 1: fp16 hi. OUTM 2: fp16 hi+lo.
// FUSE: per-tile row (max, sumexp) partials. NSTG: pipeline stages. MINB: min blocks/SM.
template <int MODE, int NPASS, int OUTM, bool FUSE, int NSTG, int MINB>
__global__ void __launch_bounds__(GEMM_THREADS, MINB)
mmagemm(const __half* __restrict__ Ahi, const __half* __restrict__ Alo,
        const __half* __restrict__ Bhi, const __half* __restrict__ Blo,
        const float* __restrict__ bias, float alpha,
        float* __restrict__ C, __half* __restrict__ Chi, __half* __restrict__ Clo,
        float* __restrict__ pm, float* __restrict__ ps,
        int M, int N, int K,
        long long sA, long long sB, long long sC) {
    constexpr int NTILE = 16384;
    constexpr int T_AHI = 0;
    constexpr int T_ALO = (NPASS == 3) ? NTILE : 0;
    constexpr int T_BHI = ((NPASS == 3) ? 2 : 1) * NTILE;
    constexpr int T_BLO = T_BHI + NTILE;
    constexpr int STAGE = (((NPASS == 3) ? 2 : 1) + ((NPASS >= 2) ? 2 : 1)) * NTILE;

    extern __shared__ char smem[];
    const uint32_t sb = smem_u32(smem);
    const int tid = threadIdx.x;
    const int wid = tid >> 5, lane = tid & 31;
    const int wm = wid >> 2, wn = wid & 3;

    Ahi += blockIdx.z * sA;  if (NPASS == 3) Alo += blockIdx.z * sA;
    Bhi += blockIdx.z * sB;  if (NPASS >= 2) Blo += blockIdx.z * sB;
    if (OUTM == 0) C += blockIdx.z * sC;
    else { Chi += blockIdx.z * sC; if (OUTM == 2) Clo += blockIdx.z * sC; }

    int m0, n0;
    if (MODE == 1) {
        int idx = blockIdx.x;
        int row = (int)((sqrtf(8.0f * idx + 1.0f) - 1.0f) * 0.5f);
        while ((row + 1) * (row + 2) / 2 <= idx) ++row;
        while (row * (row + 1) / 2 > idx) --row;
        int col = idx - row * (row + 1) / 2;
        m0 = row * BM; n0 = col * 128;
    } else {
        const int npn = N / 128, npm = M / BM;
        int pid = blockIdx.x;
        int group = GROUP_M * npn;
        int gid = pid / group;
        int first = gid * GROUP_M;
        int gsz = min(GROUP_M, npm - first);
        m0 = (first + (pid % gsz)) * BM;
        n0 = ((pid % group) / gsz) * 128;
    }

    int NC = K / BKC;
    if (MODE == 2) NC = min(NC, (m0 + BM) / BKC);

    auto load_stage = [&](int chunk, int stage) {
        const uint32_t st = sb + stage * STAGE;
        const int kk = chunk * BKC;
#pragma unroll
        for (int it = 0; it < 4; it++) {
            int idx = tid + it * 256;
            int row = idx >> 3, ch = idx & 7;
            uint32_t dst = st + (uint32_t)(row * 128 + ((ch ^ (row & 7)) * 16));
            long long ga = (long long)(m0 + row) * K + kk + ch * 8;
            cp16(dst + T_AHI, Ahi + ga);
            if (NPASS == 3) cp16(dst + T_ALO, Alo + ga);
            long long gb = (long long)(n0 + row) * K + kk + ch * 8;
            cp16(dst + T_BHI, Bhi + gb);
            if (NPASS >= 2) cp16(dst + T_BLO, Blo + gb);
        }
        asm volatile("cp.async.commit_group;" ::: "memory");
    };

    float acc[4][4][4];
#pragma unroll
    for (int a = 0; a < 4; a++)
#pragma unroll
        for (int b = 0; b < 4; b++)
#pragma unroll
            for (int c = 0; c < 4; c++) acc[a][b][c] = 0.0f;

#pragma unroll
    for (int s = 0; s < NSTG - 1; s++)
        if (s < NC) load_stage(s, s);

    for (int i = 0; i < NC; i++) {
        if (i + NSTG - 2 < NC && NSTG > 2)
            asm volatile("cp.async.wait_group %0;" :: "n"(NSTG - 2) : "memory");
        else
            asm volatile("cp.async.wait_group 0;" ::: "memory");
        __syncthreads();

        const uint32_t st = sb + (i % NSTG) * STAGE;
#pragma unroll
        for (int ks = 0; ks < 4; ks++) {
            uint32_t ah[4][4], al[4][4], bh[4][2], bl[4][2];
#pragma unroll
            for (int mt = 0; mt < 4; mt++) {
                int row = wm * 64 + mt * 16 + (lane & 15);
                uint32_t off = (uint32_t)(row * 128 + ks * 32 + ((lane >> 4) * 16));
                off = off ^ ((off >> 3) & 0x70);
                ldsm_x4(ah[mt], st + T_AHI + off);
                if (NPASS == 3) ldsm_x4(al[mt], st + T_ALO + off);
            }
#pragma unroll
            for (int nt = 0; nt < 4; nt++) {
                int row = wn * 32 + nt * 8 + (lane & 7);
                uint32_t off = (uint32_t)(row * 128 + ks * 32 + (((lane >> 3) & 1) * 16));
                off = off ^ ((off >> 3) & 0x70);
                ldsm_x2(bh[nt], st + T_BHI + off);
                if (NPASS >= 2) ldsm_x2(bl[nt], st + T_BLO + off);
            }
#pragma unroll
            for (int mt = 0; mt < 4; mt++)
#pragma unroll
                for (int nt = 0; nt < 4; nt++) {
                    mma_fp16(acc[mt][nt], ah[mt], bh[nt]);
                    if (NPASS >= 2) mma_fp16(acc[mt][nt], ah[mt], bl[nt]);
                    if (NPASS == 3) mma_fp16(acc[mt][nt], al[mt], bh[nt]);
                }
        }
        __syncthreads();
        if (i + NSTG - 1 < NC) load_stage(i + NSTG - 1, (i + NSTG - 1) % NSTG);
    }

    // finalize (alpha, bias)
    const int tg = lane >> 2;
    const int tc = (lane & 3) * 2;
#pragma unroll
    for (int mt = 0; mt < 4; mt++)
#pragma unroll
        for (int nt = 0; nt < 4; nt++) {
            int c0 = n0 + wn * 32 + nt * 8 + tc;
            float b0 = bias ? bias[c0] : 0.0f;
            float b1 = bias ? bias[c0 + 1] : 0.0f;
            acc[mt][nt][0] = alpha * acc[mt][nt][0] + b0;
            acc[mt][nt][1] = alpha * acc[mt][nt][1] + b1;
            acc[mt][nt][2] = alpha * acc[mt][nt][2] + b0;
            acc[mt][nt][3] = alpha * acc[mt][nt][3] + b1;
        }

    // stores
#pragma unroll
    for (int mt = 0; mt < 4; mt++)
#pragma unroll
        for (int nt = 0; nt < 4; nt++) {
            int r0 = m0 + wm * 64 + mt * 16 + tg;
            int c0 = n0 + wn * 32 + nt * 8 + tc;
            if (OUTM == 0) {
                *(float2*)(C + (long long)r0 * N + c0) = make_float2(acc[mt][nt][0], acc[mt][nt][1]);
                *(float2*)(C + (long long)(r0 + 8) * N + c0) = make_float2(acc[mt][nt][2], acc[mt][nt][3]);
            } else if (OUTM == 1) {
                *(__half2*)(Chi + (long long)r0 * N + c0) =
                    __half2(__float2half_rn(acc[mt][nt][0]), __float2half_rn(acc[mt][nt][1]));
                *(__half2*)(Chi + (long long)(r0 + 8) * N + c0) =
                    __half2(__float2half_rn(acc[mt][nt][2]), __float2half_rn(acc[mt][nt][3]));
            } else {
                __half h0, l0, h1, l1;
                split_h(acc[mt][nt][0], h0, l0); split_h(acc[mt][nt][1], h1, l1);
                *(__half2*)(Chi + (long long)r0 * N + c0) = __half2(h0, h1);
                *(__half2*)(Clo + (long long)r0 * N + c0) = __half2(l0, l1);
                split_h(acc[mt][nt][2], h0, l0); split_h(acc[mt][nt][3], h1, l1);
                *(__half2*)(Chi + (long long)(r0 + 8) * N + c0) = __half2(h0, h1);
                *(__half2*)(Clo + (long long)(r0 + 8) * N + c0) = __half2(l0, l1);
            }
        }

    // fused per-tile row logsumexp partials
    if (FUSE) {
        float* smM = (float*)smem;            // [4][128]
        float* smS = smM + 512;
        float rm[8], rs[8];
#pragma unroll
        for (int mt = 0; mt < 4; mt++)
#pragma unroll
            for (int hf = 0; hf < 2; hf++) {
                float m = -INFINITY;
#pragma unroll
                for (int nt = 0; nt < 4; nt++) {
                    m = fmaxf(m, acc[mt][nt][hf * 2 + 0]);
                    m = fmaxf(m, acc[mt][nt][hf * 2 + 1]);
                }
                rm[mt * 2 + hf] = m;
            }
#pragma unroll
        for (int s = 0; s < 8; s++) {
            rm[s] = fmaxf(rm[s], __shfl_xor_sync(0xffffffffu, rm[s], 1));
            rm[s] = fmaxf(rm[s], __shfl_xor_sync(0xffffffffu, rm[s], 2));
        }
#pragma unroll
        for (int mt = 0; mt < 4; mt++)
#pragma unroll
            for (int hf = 0; hf < 2; hf++) {
                float m = rm[mt * 2 + hf], s = 0.0f;
#pragma unroll
                for (int nt = 0; nt < 4; nt++) {
                    s += __expf(acc[mt][nt][hf * 2 + 0] - m);
                    s += __expf(acc[mt][nt][hf * 2 + 1] - m);
                }
                rs[mt * 2 + hf] = s;
            }
#pragma unroll
        for (int s = 0; s < 8; s++) {
            rs[s] += __shfl_xor_sync(0xffffffffu, rs[s], 1);
            rs[s] += __shfl_xor_sync(0xffffffffu, rs[s], 2);
        }
        __syncthreads();
        if ((lane & 3) == 0) {
#pragma unroll
            for (int mt = 0; mt < 4; mt++)
#pragma unroll
                for (int hf = 0; hf < 2; hf++) {
                    int rin = wm * 64 + mt * 16 + hf * 8 + tg;
                    smM[wn * 128 + rin] = rm[mt * 2 + hf];
                    smS[wn * 128 + rin] = rs[mt * 2 + hf];
                }
        }
        __syncthreads();
        if (tid < 128) {
            float M4 = smM[tid];
            M4 = fmaxf(M4, smM[128 + tid]);
            M4 = fmaxf(M4, smM[256 + tid]);
            M4 = fmaxf(M4, smM[384 + tid]);
            float S4 = smS[tid] * __expf(smM[tid] - M4)
                     + smS[128 + tid] * __expf(smM[128 + tid] - M4)
                     + smS[256 + tid] * __expf(smM[256 + tid] - M4)
                     + smS[384 + tid] * __expf(smM[384 + tid] - M4);
            long long o = (long long)(m0 + tid) * (N / 128) + n0 / 128;
            pm[o] = M4; ps[o] = S4;
        }
    }
}

// ---------------- embedding (split fp16) ----------------
__global__ void embed_split_kernel(const int* __restrict__ x,
                                   const float* __restrict__ tok,
                                   const float* __restrict__ pos,
                                   __half* __restrict__ hhi, __half* __restrict__ hlo) {
    int i = blockIdx.x * blockDim.x + threadIdx.x;
    if (i >= NTOK * DD) return;
    int row = i >> 10;
    int d = i & 1023;
    int t = row & (TT - 1);
    float v = tok[(long long)x[row] * DD + d] + pos[t * DD + d];
    __half hi, lo;
    split_h(v, hi, lo);
    hhi[i] = hi; hlo[i] = lo;
}

// ---------------- transpose + split (lo optional) ----------------
__global__ void transpose_split_kernel(const float* __restrict__ in,
                                       __half* __restrict__ ohi, __half* __restrict__ olo,
                                       int R, int C, long long sIn, long long sOut) {
    __shared__ float tbuf[32][33];
    in += blockIdx.z * sIn;
    ohi += blockIdx.z * sOut;
    if (olo) olo += blockIdx.z * sOut;
    int c0 = blockIdx.x * 32, r0 = blockIdx.y * 32;
    int tx = threadIdx.x, ty = threadIdx.y;
#pragma unroll
    for (int i = 0; i < 32; i += 8)
        tbuf[ty + i][tx] = in[(long long)(r0 + ty + i) * C + c0 + tx];
    __syncthreads();
#pragma unroll
    for (int i = 0; i < 32; i += 8) {
        float v = tbuf[tx][ty + i];
        long long o = (long long)(c0 + ty + i) * R + r0 + tx;
        if (olo) {
            __half hi, lo;
            split_h(v, hi, lo);
            ohi[o] = hi; olo[o] = lo;
        } else {
            ohi[o] = __float2half_rn(v);
        }
    }
}

// ---------------- reductions ----------------
__device__ __forceinline__ float blockMax(float v, float* red) {
#pragma unroll
    for (int o = 16; o; o >>= 1) v = fmaxf(v, __shfl_xor_sync(0xffffffffu, v, o));
    if ((threadIdx.x & 31) == 0) red[threadIdx.x >> 5] = v;
    __syncthreads();
    float r = red[0];
#pragma unroll
    for (int i = 1; i < 8; i++) r = fmaxf(r, red[i]);
    __syncthreads();
    return r;
}
__device__ __forceinline__ float blockSum(float v, float* red) {
#pragma unroll
    for (int o = 16; o; o >>= 1) v += __shfl_xor_sync(0xffffffffu, v, o);
    if ((threadIdx.x & 31) == 0) red[threadIdx.x >> 5] = v;
    __syncthreads();
    float r = red[0];
#pragma unroll
    for (int i = 1; i < 8; i++) r += red[i];
    __syncthreads();
    return r;
}

// ---------------- causal softmax -> split fp16 ----------------
__global__ void __launch_bounds__(256)
softmax_split_kernel(const float* __restrict__ att,
                     __half* __restrict__ ahi, __half* __restrict__ alo) {
    __shared__ float red[8];
    int row = blockIdx.x;
    int i = row & (TT - 1);
    const float* p = att + (long long)row * TT;
    __half* ph = ahi + (long long)row * TT;
    __half* pl = alo + (long long)row * TT;
    int tid = threadIdx.x;

    float m = -INFINITY;
    for (int j = tid; j <= i; j += 256) m = fmaxf(m, p[j]);
    m = blockMax(m, red);

    float s = 0.0f;
    for (int j = tid; j <= i; j += 256) s += expf(p[j] - m);
    s = blockSum(s, red);
    float inv = 1.0f / s;

    for (int j = tid; j <= i; j += 256) {
        float e = expf(p[j] - m) * inv;
        __half hi, lo;
        split_h(e, hi, lo);
        ph[j] = hi; pl[j] = lo;
    }
    int jend = ((i >> 7) + 1) << 7;
    __half z = __float2half(0.0f);
    for (int j = i + 1 + tid; j < jend; j += 256) { ph[j] = z; pl[j] = z; }
}

// ---------------- rowloss from fused partials ----------------
__global__ void __launch_bounds__(32)
rowloss_partials_kernel(const float* __restrict__ pm, const float* __restrict__ ps,
                        const float* __restrict__ logits, const int* __restrict__ target,
                        float* __restrict__ rowloss) {
    int row = blockIdx.x;
    int lane = threadIdx.x;
    float m = -INFINITY, s = 0.0f;
    for (int t = lane; t < LM_NTILES; t += 32) {
        long long o = (long long)row * LM_NTILES + t;
        float tm = pm[o], ts = ps[o];
        float nm = fmaxf(m, tm);
        s = s * __expf(m - nm) + ts * __expf(tm - nm);
        m = nm;
    }
#pragma unroll
    for (int o = 16; o; o >>= 1) {
        float om = __shfl_xor_sync(0xffffffffu, m, o);
        float os = __shfl_xor_sync(0xffffffffu, s, o);
        float nm = fmaxf(m, om);
        s = s * __expf(m - nm) + os * __expf(om - nm);
        m = nm;
    }
    if (lane == 0)
        rowloss[row] = m + logf(s) - logits[(long long)row * VV + target[row]];
}

__global__ void __launch_bounds__(256)
loss_reduce_kernel(const float* __restrict__ rowloss, float* __restrict__ out) {
    __shared__ float red[8];
    float s = 0.0f;
    for (int r = threadIdx.x; r < NTOK; r += 256) s += rowloss[r];
    s = blockSum(s, red);
    if (threadIdx.x == 0) out[0] = s / (float)NTOK;
}

// ---------------- launch ----------------
extern "C" void kernel_launch(void* const* d_in, const int* in_sizes, int n_in,
                              void* d_out, int out_size) {
    const int*   x      = (const int*)d_in[0];
    const int*   target = (const int*)d_in[1];
    const float* tok    = (const float*)d_in[2];
    const float* pos    = (const float*)d_in[3];
    const float* Wq     = (const float*)d_in[4];
    const float* bq     = (const float*)d_in[5];
    const float* Wk     = (const float*)d_in[6];
    const float* bk     = (const float*)d_in[7];
    const float* Wv     = (const float*)d_in[8];
    const float* bv     = (const float*)d_in[9];
    const float* W_lm   = (const float*)d_in[10];
    const float* b_lm   = (const float*)d_in[11];
    float* out = (float*)d_out;

    const int SM3 = 3 * 4 * 16384;   // 196608 (3-pass, 3 stages)
    const int SM2 = 2 * 3 * 16384;   //  98304 (2-pass, 2 stages, 2 CTAs/SM)
    const int SM1 = 3 * 2 * 16384;   //  98304 (1-pass, 3 stages, 2 CTAs/SM)

    cudaFuncSetAttribute((const void*)mmagemm<0,3,2,false,3,1>, cudaFuncAttributeMaxDynamicSharedMemorySize, SM3);
    cudaFuncSetAttribute((const void*)mmagemm<0,2,0,false,2,2>, cudaFuncAttributeMaxDynamicSharedMemorySize, SM2);
    cudaFuncSetAttribute((const void*)mmagemm<1,3,0,false,3,1>, cudaFuncAttributeMaxDynamicSharedMemorySize, SM3);
    cudaFuncSetAttribute((const void*)mmagemm<2,3,1,false,3,1>, cudaFuncAttributeMaxDynamicSharedMemorySize, SM3);
    cudaFuncSetAttribute((const void*)mmagemm<0,1,0,true,3,2>,  cudaFuncAttributeMaxDynamicSharedMemorySize, SM1);

    __half *h_hi, *h_lo, *q_hi, *q_lo, *k_hi, *k_lo, *vT_hi, *vT_lo;
    __half *att_hi, *att_lo, *y_hi;
    __half *WqT_hi, *WqT_lo, *WkT_hi, *WkT_lo, *WvT_hi, *WvT_lo, *WlmT_hi;
    float *v, *att, *rowloss, *pm, *ps;
    cudaGetSymbolAddress((void**)&h_hi, g_h_hi);   cudaGetSymbolAddress((void**)&h_lo, g_h_lo);
    cudaGetSymbolAddress((void**)&q_hi, g_q_hi);   cudaGetSymbolAddress((void**)&q_lo, g_q_lo);
    cudaGetSymbolAddress((void**)&k_hi, g_k_hi);   cudaGetSymbolAddress((void**)&k_lo, g_k_lo);
    cudaGetSymbolAddress((void**)&v, g_v);
    cudaGetSymbolAddress((void**)&vT_hi, g_vT_hi); cudaGetSymbolAddress((void**)&vT_lo, g_vT_lo);
    cudaGetSymbolAddress((void**)&att, g_att);
    cudaGetSymbolAddress((void**)&att_hi, g_att_hi); cudaGetSymbolAddress((void**)&att_lo, g_att_lo);
    cudaGetSymbolAddress((void**)&y_hi, g_y_hi);
    cudaGetSymbolAddress((void**)&WqT_hi, g_WqT_hi); cudaGetSymbolAddress((void**)&WqT_lo, g_WqT_lo);
    cudaGetSymbolAddress((void**)&WkT_hi, g_WkT_hi); cudaGetSymbolAddress((void**)&WkT_lo, g_WkT_lo);
    cudaGetSymbolAddress((void**)&WvT_hi, g_WvT_hi); cudaGetSymbolAddress((void**)&WvT_lo, g_WvT_lo);
    cudaGetSymbolAddress((void**)&WlmT_hi, g_WlmT_hi);
    cudaGetSymbolAddress((void**)&pm, g_pm);       cudaGetSymbolAddress((void**)&ps, g_ps);
    cudaGetSymbolAddress((void**)&rowloss, g_rowloss);

    dim3 tb(32, 8);

    embed_split_kernel<<<(NTOK * DD + 255) / 256, 256>>>(x, tok, pos, h_hi, h_lo);

    transpose_split_kernel<<<dim3(DD / 32, DD / 32, 1), tb>>>(Wq, WqT_hi, WqT_lo, DD, DD, 0, 0);
    transpose_split_kernel<<<dim3(DD / 32, DD / 32, 1), tb>>>(Wk, WkT_hi, WkT_lo, DD, DD, 0, 0);
    transpose_split_kernel<<<dim3(DD / 32, DD / 32, 1), tb>>>(Wv, WvT_hi, WvT_lo, DD, DD, 0, 0);
    transpose_split_kernel<<<dim3(VV / 32, DD / 32, 1), tb>>>(W_lm, WlmT_hi, nullptr, DD, VV, 0, 0);

    // q, k: 3-pass split-out; v: 2-pass fp32-out (2 CTAs/SM)
    {
        dim3 grid((NTOK / BM) * (DD / 128), 1, 1);
        mmagemm<0,3,2,false,3,1><<<grid, GEMM_THREADS, SM3>>>(h_hi, h_lo, WqT_hi, WqT_lo, bq, 1.0f,
            nullptr, q_hi, q_lo, nullptr, nullptr, NTOK, DD, DD, 0, 0, 0);
        mmagemm<0,3,2,false,3,1><<<grid, GEMM_THREADS, SM3>>>(h_hi, h_lo, WkT_hi, WkT_lo, bk, 1.0f,
            nullptr, k_hi, k_lo, nullptr, nullptr, NTOK, DD, DD, 0, 0, 0);
        mmagemm<0,2,0,false,2,2><<<grid, GEMM_THREADS, SM2>>>(h_hi, nullptr, WvT_hi, WvT_lo, bv, 1.0f,
            v, nullptr, nullptr, nullptr, nullptr, NTOK, DD, DD, 0, 0, 0);
    }

    transpose_split_kernel<<<dim3(DD / 32, TT / 32, BB), tb>>>(v, vT_hi, vT_lo, TT, DD,
        (long long)TT * DD, (long long)TT * DD);

    // scores: 3-pass, lower-triangular tiles only
    {
        dim3 grid(136, 1, BB);
        mmagemm<1,3,0,false,3,1><<<grid, GEMM_THREADS, SM3>>>(q_hi, q_lo, k_hi, k_lo, nullptr, 0.03125f,
            att, nullptr, nullptr, nullptr, nullptr, TT, TT, DD,
            (long long)TT * DD, (long long)TT * DD, (long long)TT * TT);
    }

    softmax_split_kernel<<<NTOK, 256>>>(att, att_hi, att_lo);

    // y = attn @ v: 3-pass, K truncated, hi-only output
    {
        dim3 grid((TT / BM) * (DD / 128), 1, BB);
        mmagemm<2,3,1,false,3,1><<<grid, GEMM_THREADS, SM3>>>(att_hi, att_lo, vT_hi, vT_lo, nullptr, 1.0f,
            nullptr, y_hi, nullptr, nullptr, nullptr, TT, DD, TT,
            (long long)TT * TT, (long long)TT * DD, (long long)TT * DD);
    }

    // logits: 1-pass fp16, 2 CTAs/SM + fused loss partials
    {
        dim3 grid((NTOK / BM) * (VV / 128), 1, 1);
        mmagemm<0,1,0,true,3,2><<<grid, GEMM_THREADS, SM1>>>(y_hi, nullptr, WlmT_hi, nullptr, b_lm, 1.0f,
            out, nullptr, nullptr, pm, ps, NTOK, VV, DD, 0, 0, 0);
    }

    rowloss_partials_kernel<<<NTOK, 32>>>(pm, ps, out, target, rowloss);
    if ((long long)out_size > NLOGITS) {
        loss_reduce_kernel<<<1, 256>>>(rowloss, out + NLOGITS);
    }
}

// round 8
// speedup vs baseline: 1.1001x; 1.0769x over previous
#include <cuda_runtime.h>
#include <cuda_fp16.h>
#include <math.h>
#include <stdint.h>

// ---------------- problem dims ----------------
#define BB 4
#define TT 2048
#define DD 1024
#define VV 32000
#define NTOK (BB * TT)                 // 8192
#define NLOGITS 262144000LL
#define ATT_ELEMS ((long long)BB * TT * TT)
#define LM_NTILES (VV / 128)           // 250

// ---------------- GEMM tiling ----------------
#define BM 128
#define BKC 64
#define GROUP_M 8
#define GEMM_THREADS 256

// ---------------- scratch ----------------
__device__ __half g_h_hi[NTOK * DD],  g_h_lo[NTOK * DD];
__device__ __half g_q_hi[NTOK * DD];
__device__ __half g_k_hi[NTOK * DD],  g_k_lo[NTOK * DD];
__device__ float  g_v[NTOK * DD];
__device__ __half g_vT_hi[NTOK * DD], g_vT_lo[NTOK * DD];
__device__ float  g_att[ATT_ELEMS];
__device__ __half g_att_hi[ATT_ELEMS], g_att_lo[ATT_ELEMS];
__device__ __half g_y_hi[NTOK * DD];
__device__ __half g_WqT_hi[DD * DD],  g_WqT_lo[DD * DD];
__device__ __half g_WkT_hi[DD * DD],  g_WkT_lo[DD * DD];
__device__ __half g_WvT_hi[DD * DD],  g_WvT_lo[DD * DD];
__device__ __half g_WlmT_hi[(long long)VV * DD];
__device__ float  g_pm[(long long)NTOK * LM_NTILES];
__device__ float  g_ps[(long long)NTOK * LM_NTILES];
__device__ float  g_rowloss[NTOK];

// ---------------- helpers ----------------
__device__ __forceinline__ uint32_t smem_u32(const void* p) {
    uint32_t a;
    asm("{ .reg .u64 t; cvta.to.shared.u64 t, %1; cvt.u32.u64 %0, t; }" : "=r"(a) : "l"(p));
    return a;
}
__device__ __forceinline__ void cp16(uint32_t dst, const void* src) {
    asm volatile("cp.async.cg.shared.global [%0], [%1], 16;" :: "r"(dst), "l"(src));
}
__device__ __forceinline__ void ldsm_x4(uint32_t* r, uint32_t addr) {
    asm volatile("ldmatrix.sync.aligned.m8n8.x4.shared.b16 {%0,%1,%2,%3}, [%4];"
                 : "=r"(r[0]), "=r"(r[1]), "=r"(r[2]), "=r"(r[3]) : "r"(addr));
}
__device__ __forceinline__ void ldsm_x2(uint32_t* r, uint32_t addr) {
    asm volatile("ldmatrix.sync.aligned.m8n8.x2.shared.b16 {%0,%1}, [%2];"
                 : "=r"(r[0]), "=r"(r[1]) : "r"(addr));
}
__device__ __forceinline__ void mma_fp16(float* c, const uint32_t* a, const uint32_t* b) {
    asm volatile("mma.sync.aligned.m16n8k16.row.col.f32.f16.f16.f32 "
                 "{%0,%1,%2,%3}, {%4,%5,%6,%7}, {%8,%9}, {%0,%1,%2,%3};"
                 : "+f"(c[0]), "+f"(c[1]), "+f"(c[2]), "+f"(c[3])
                 : "r"(a[0]), "r"(a[1]), "r"(a[2]), "r"(a[3]), "r"(b[0]), "r"(b[1]));
}
__device__ __forceinline__ void split_h(float x, __half& hi, __half& lo) {
    hi = __float2half_rn(x);
    lo = __float2half_rn(x - __half2float(hi));
}

// ---------------- split-fp16 HMMA GEMM (BN=128) ----------------
// MODE 0: normal. MODE 1: lower-triangular tiles. MODE 2: K truncated at m0+BM.
// NPASS 3: hh + h*Blo + Alo*h.  NPASS 2: hh + h*Blo.  NPASS 1: hh.
// OUTM 0: f32. OUTM 1: fp16 hi. OUTM 2: fp16 hi+lo.
// FUSE: per-tile row (max, sumexp) partials. NSTG: pipeline stages. MINB: min blocks/SM.
template <int MODE, int NPASS, int OUTM, bool FUSE, int NSTG, int MINB>
__global__ void __launch_bounds__(GEMM_THREADS, MINB)
mmagemm(const __half* __restrict__ Ahi, const __half* __restrict__ Alo,
        const __half* __restrict__ Bhi, const __half* __restrict__ Blo,
        const float* __restrict__ bias, float alpha,
        float* __restrict__ C, __half* __restrict__ Chi, __half* __restrict__ Clo,
        float* __restrict__ pm, float* __restrict__ ps,
        int M, int N, int K,
        long long sA, long long sB, long long sC) {
    constexpr int NTILE = 16384;
    constexpr int T_AHI = 0;
    constexpr int T_ALO = (NPASS == 3) ? NTILE : 0;
    constexpr int T_BHI = ((NPASS == 3) ? 2 : 1) * NTILE;
    constexpr int T_BLO = T_BHI + NTILE;
    constexpr int STAGE = (((NPASS == 3) ? 2 : 1) + ((NPASS >= 2) ? 2 : 1)) * NTILE;

    extern __shared__ char smem[];
    const uint32_t sb = smem_u32(smem);
    const int tid = threadIdx.x;
    const int wid = tid >> 5, lane = tid & 31;
    const int wm = wid >> 2, wn = wid & 3;

    Ahi += blockIdx.z * sA;  if (NPASS == 3) Alo += blockIdx.z * sA;
    Bhi += blockIdx.z * sB;  if (NPASS >= 2) Blo += blockIdx.z * sB;
    if (OUTM == 0) C += blockIdx.z * sC;
    else { Chi += blockIdx.z * sC; if (OUTM == 2) Clo += blockIdx.z * sC; }

    int m0, n0;
    if (MODE == 1) {
        int idx = blockIdx.x;
        int row = (int)((sqrtf(8.0f * idx + 1.0f) - 1.0f) * 0.5f);
        while ((row + 1) * (row + 2) / 2 <= idx) ++row;
        while (row * (row + 1) / 2 > idx) --row;
        int col = idx - row * (row + 1) / 2;
        m0 = row * BM; n0 = col * 128;
    } else {
        const int npn = N / 128, npm = M / BM;
        int pid = blockIdx.x;
        int group = GROUP_M * npn;
        int gid = pid / group;
        int first = gid * GROUP_M;
        int gsz = min(GROUP_M, npm - first);
        m0 = (first + (pid % gsz)) * BM;
        n0 = ((pid % group) / gsz) * 128;
    }

    int NC = K / BKC;
    if (MODE == 2) NC = min(NC, (m0 + BM) / BKC);

    auto load_stage = [&](int chunk, int stage) {
        const uint32_t st = sb + stage * STAGE;
        const int kk = chunk * BKC;
#pragma unroll
        for (int it = 0; it < 4; it++) {
            int idx = tid + it * 256;
            int row = idx >> 3, ch = idx & 7;
            uint32_t dst = st + (uint32_t)(row * 128 + ((ch ^ (row & 7)) * 16));
            long long ga = (long long)(m0 + row) * K + kk + ch * 8;
            cp16(dst + T_AHI, Ahi + ga);
            if (NPASS == 3) cp16(dst + T_ALO, Alo + ga);
            long long gb = (long long)(n0 + row) * K + kk + ch * 8;
            cp16(dst + T_BHI, Bhi + gb);
            if (NPASS >= 2) cp16(dst + T_BLO, Blo + gb);
        }
        asm volatile("cp.async.commit_group;" ::: "memory");
    };

    float acc[4][4][4];
#pragma unroll
    for (int a = 0; a < 4; a++)
#pragma unroll
        for (int b = 0; b < 4; b++)
#pragma unroll
            for (int c = 0; c < 4; c++) acc[a][b][c] = 0.0f;

#pragma unroll
    for (int s = 0; s < NSTG - 1; s++)
        if (s < NC) load_stage(s, s);

    for (int i = 0; i < NC; i++) {
        // wait for stage i, then prefetch stage i+NSTG-1 BEFORE computing
        if (i + NSTG - 2 < NC)
            asm volatile("cp.async.wait_group %0;" :: "n"(NSTG - 2) : "memory");
        else
            asm volatile("cp.async.wait_group 0;" ::: "memory");
        __syncthreads();
        if (i + NSTG - 1 < NC) load_stage(i + NSTG - 1, (i + NSTG - 1) % NSTG);

        const uint32_t st = sb + (i % NSTG) * STAGE;
#pragma unroll
        for (int ks = 0; ks < 4; ks++) {
            uint32_t ah[4][4], al[4][4], bh[4][2], bl[4][2];
#pragma unroll
            for (int mt = 0; mt < 4; mt++) {
                int row = wm * 64 + mt * 16 + (lane & 15);
                uint32_t off = (uint32_t)(row * 128 + ks * 32 + ((lane >> 4) * 16));
                off = off ^ ((off >> 3) & 0x70);
                ldsm_x4(ah[mt], st + T_AHI + off);
                if (NPASS == 3) ldsm_x4(al[mt], st + T_ALO + off);
            }
#pragma unroll
            for (int nt = 0; nt < 4; nt++) {
                int row = wn * 32 + nt * 8 + (lane & 7);
                uint32_t off = (uint32_t)(row * 128 + ks * 32 + (((lane >> 3) & 1) * 16));
                off = off ^ ((off >> 3) & 0x70);
                ldsm_x2(bh[nt], st + T_BHI + off);
                if (NPASS >= 2) ldsm_x2(bl[nt], st + T_BLO + off);
            }
#pragma unroll
            for (int mt = 0; mt < 4; mt++)
#pragma unroll
                for (int nt = 0; nt < 4; nt++) {
                    mma_fp16(acc[mt][nt], ah[mt], bh[nt]);
                    if (NPASS >= 2) mma_fp16(acc[mt][nt], ah[mt], bl[nt]);
                    if (NPASS == 3) mma_fp16(acc[mt][nt], al[mt], bh[nt]);
                }
        }
        __syncthreads();
    }

    // finalize (alpha, bias)
    const int tg = lane >> 2;
    const int tc = (lane & 3) * 2;
#pragma unroll
    for (int mt = 0; mt < 4; mt++)
#pragma unroll
        for (int nt = 0; nt < 4; nt++) {
            int c0 = n0 + wn * 32 + nt * 8 + tc;
            float b0 = bias ? bias[c0] : 0.0f;
            float b1 = bias ? bias[c0 + 1] : 0.0f;
            acc[mt][nt][0] = alpha * acc[mt][nt][0] + b0;
            acc[mt][nt][1] = alpha * acc[mt][nt][1] + b1;
            acc[mt][nt][2] = alpha * acc[mt][nt][2] + b0;
            acc[mt][nt][3] = alpha * acc[mt][nt][3] + b1;
        }

    // stores
#pragma unroll
    for (int mt = 0; mt < 4; mt++)
#pragma unroll
        for (int nt = 0; nt < 4; nt++) {
            int r0 = m0 + wm * 64 + mt * 16 + tg;
            int c0 = n0 + wn * 32 + nt * 8 + tc;
            if (OUTM == 0) {
                *(float2*)(C + (long long)r0 * N + c0) = make_float2(acc[mt][nt][0], acc[mt][nt][1]);
                *(float2*)(C + (long long)(r0 + 8) * N + c0) = make_float2(acc[mt][nt][2], acc[mt][nt][3]);
            } else if (OUTM == 1) {
                *(__half2*)(Chi + (long long)r0 * N + c0) =
                    __half2(__float2half_rn(acc[mt][nt][0]), __float2half_rn(acc[mt][nt][1]));
                *(__half2*)(Chi + (long long)(r0 + 8) * N + c0) =
                    __half2(__float2half_rn(acc[mt][nt][2]), __float2half_rn(acc[mt][nt][3]));
            } else {
                __half h0, l0, h1, l1;
                split_h(acc[mt][nt][0], h0, l0); split_h(acc[mt][nt][1], h1, l1);
                *(__half2*)(Chi + (long long)r0 * N + c0) = __half2(h0, h1);
                *(__half2*)(Clo + (long long)r0 * N + c0) = __half2(l0, l1);
                split_h(acc[mt][nt][2], h0, l0); split_h(acc[mt][nt][3], h1, l1);
                *(__half2*)(Chi + (long long)(r0 + 8) * N + c0) = __half2(h0, h1);
                *(__half2*)(Clo + (long long)(r0 + 8) * N + c0) = __half2(l0, l1);
            }
        }

    // fused per-tile row logsumexp partials
    if (FUSE) {
        float* smM = (float*)smem;            // [4][128]
        float* smS = smM + 512;
        float rm[8], rs[8];
#pragma unroll
        for (int mt = 0; mt < 4; mt++)
#pragma unroll
            for (int hf = 0; hf < 2; hf++) {
                float m = -INFINITY;
#pragma unroll
                for (int nt = 0; nt < 4; nt++) {
                    m = fmaxf(m, acc[mt][nt][hf * 2 + 0]);
                    m = fmaxf(m, acc[mt][nt][hf * 2 + 1]);
                }
                rm[mt * 2 + hf] = m;
            }
#pragma unroll
        for (int s = 0; s < 8; s++) {
            rm[s] = fmaxf(rm[s], __shfl_xor_sync(0xffffffffu, rm[s], 1));
            rm[s] = fmaxf(rm[s], __shfl_xor_sync(0xffffffffu, rm[s], 2));
        }
#pragma unroll
        for (int mt = 0; mt < 4; mt++)
#pragma unroll
            for (int hf = 0; hf < 2; hf++) {
                float m = rm[mt * 2 + hf], s = 0.0f;
#pragma unroll
                for (int nt = 0; nt < 4; nt++) {
                    s += __expf(acc[mt][nt][hf * 2 + 0] - m);
                    s += __expf(acc[mt][nt][hf * 2 + 1] - m);
                }
                rs[mt * 2 + hf] = s;
            }
#pragma unroll
        for (int s = 0; s < 8; s++) {
            rs[s] += __shfl_xor_sync(0xffffffffu, rs[s], 1);
            rs[s] += __shfl_xor_sync(0xffffffffu, rs[s], 2);
        }
        __syncthreads();
        if ((lane & 3) == 0) {
#pragma unroll
            for (int mt = 0; mt < 4; mt++)
#pragma unroll
                for (int hf = 0; hf < 2; hf++) {
                    int rin = wm * 64 + mt * 16 + hf * 8 + tg;
                    smM[wn * 128 + rin] = rm[mt * 2 + hf];
                    smS[wn * 128 + rin] = rs[mt * 2 + hf];
                }
        }
        __syncthreads();
        if (tid < 128) {
            float M4 = smM[tid];
            M4 = fmaxf(M4, smM[128 + tid]);
            M4 = fmaxf(M4, smM[256 + tid]);
            M4 = fmaxf(M4, smM[384 + tid]);
            float S4 = smS[tid] * __expf(smM[tid] - M4)
                     + smS[128 + tid] * __expf(smM[128 + tid] - M4)
                     + smS[256 + tid] * __expf(smM[256 + tid] - M4)
                     + smS[384 + tid] * __expf(smM[384 + tid] - M4);
            long long o = (long long)(m0 + tid) * (N / 128) + n0 / 128;
            pm[o] = M4; ps[o] = S4;
        }
    }
}

// ---------------- embedding (split fp16) ----------------
__global__ void embed_split_kernel(const int* __restrict__ x,
                                   const float* __restrict__ tok,
                                   const float* __restrict__ pos,
                                   __half* __restrict__ hhi, __half* __restrict__ hlo) {
    int i = blockIdx.x * blockDim.x + threadIdx.x;
    if (i >= NTOK * DD) return;
    int row = i >> 10;
    int d = i & 1023;
    int t = row & (TT - 1);
    float v = tok[(long long)x[row] * DD + d] + pos[t * DD + d];
    __half hi, lo;
    split_h(v, hi, lo);
    hhi[i] = hi; hlo[i] = lo;
}

// ---------------- transpose + split: 64(R) x 32(C) tiles, half2 stores ----------------
__global__ void __launch_bounds__(256)
transpose_split_kernel(const float* __restrict__ in,
                       __half* __restrict__ ohi, __half* __restrict__ olo,
                       int R, int C, long long sIn, long long sOut) {
    __shared__ float tbuf[64][33];
    in += blockIdx.z * sIn;
    ohi += blockIdx.z * sOut;
    if (olo) olo += blockIdx.z * sOut;
    int c0 = blockIdx.x * 32, r0 = blockIdx.y * 64;
    int tx = threadIdx.x, ty = threadIdx.y;   // 32 x 8
#pragma unroll
    for (int i = 0; i < 64; i += 8)
        tbuf[ty + i][tx] = in[(long long)(r0 + ty + i) * C + c0 + tx];
    __syncthreads();
#pragma unroll
    for (int i = 0; i < 32; i += 8) {
        int c = ty + i;
        float v0 = tbuf[2 * tx][c], v1 = tbuf[2 * tx + 1][c];
        long long o = (long long)(c0 + c) * R + r0 + 2 * tx;
        __half h0, l0, h1, l1;
        split_h(v0, h0, l0); split_h(v1, h1, l1);
        *(__half2*)(ohi + o) = __half2(h0, h1);
        if (olo) *(__half2*)(olo + o) = __half2(l0, l1);
    }
}

// ---------------- reductions ----------------
__device__ __forceinline__ float blockMax(float v, float* red) {
#pragma unroll
    for (int o = 16; o; o >>= 1) v = fmaxf(v, __shfl_xor_sync(0xffffffffu, v, o));
    if ((threadIdx.x & 31) == 0) red[threadIdx.x >> 5] = v;
    __syncthreads();
    float r = red[0];
#pragma unroll
    for (int i = 1; i < 8; i++) r = fmaxf(r, red[i]);
    __syncthreads();
    return r;
}
__device__ __forceinline__ float blockSum(float v, float* red) {
#pragma unroll
    for (int o = 16; o; o >>= 1) v += __shfl_xor_sync(0xffffffffu, v, o);
    if ((threadIdx.x & 31) == 0) red[threadIdx.x >> 5] = v;
    __syncthreads();
    float r = red[0];
#pragma unroll
    for (int i = 1; i < 8; i++) r += red[i];
    __syncthreads();
    return r;
}

// ---------------- causal softmax -> split fp16 ----------------
__global__ void __launch_bounds__(256)
softmax_split_kernel(const float* __restrict__ att,
                     __half* __restrict__ ahi, __half* __restrict__ alo) {
    __shared__ float red[8];
    int row = blockIdx.x;
    int i = row & (TT - 1);
    const float* p = att + (long long)row * TT;
    __half* ph = ahi + (long long)row * TT;
    __half* pl = alo + (long long)row * TT;
    int tid = threadIdx.x;

    float m = -INFINITY;
    for (int j = tid; j <= i; j += 256) m = fmaxf(m, p[j]);
    m = blockMax(m, red);

    float s = 0.0f;
    for (int j = tid; j <= i; j += 256) s += expf(p[j] - m);
    s = blockSum(s, red);
    float inv = 1.0f / s;

    for (int j = tid; j <= i; j += 256) {
        float e = expf(p[j] - m) * inv;
        __half hi, lo;
        split_h(e, hi, lo);
        ph[j] = hi; pl[j] = lo;
    }
    int jend = ((i >> 7) + 1) << 7;
    __half z = __float2half(0.0f);
    for (int j = i + 1 + tid; j < jend; j += 256) { ph[j] = z; pl[j] = z; }
}

// ---------------- rowloss from fused partials ----------------
__global__ void __launch_bounds__(32)
rowloss_partials_kernel(const float* __restrict__ pm, const float* __restrict__ ps,
                        const float* __restrict__ logits, const int* __restrict__ target,
                        float* __restrict__ rowloss) {
    int row = blockIdx.x;
    int lane = threadIdx.x;
    float m = -INFINITY, s = 0.0f;
    for (int t = lane; t < LM_NTILES; t += 32) {
        long long o = (long long)row * LM_NTILES + t;
        float tm = pm[o], ts = ps[o];
        float nm = fmaxf(m, tm);
        s = s * __expf(m - nm) + ts * __expf(tm - nm);
        m = nm;
    }
#pragma unroll
    for (int o = 16; o; o >>= 1) {
        float om = __shfl_xor_sync(0xffffffffu, m, o);
        float os = __shfl_xor_sync(0xffffffffu, s, o);
        float nm = fmaxf(m, om);
        s = s * __expf(m - nm) + os * __expf(om - nm);
        m = nm;
    }
    if (lane == 0)
        rowloss[row] = m + logf(s) - logits[(long long)row * VV + target[row]];
}

__global__ void __launch_bounds__(256)
loss_reduce_kernel(const float* __restrict__ rowloss, float* __restrict__ out) {
    __shared__ float red[8];
    float s = 0.0f;
    for (int r = threadIdx.x; r < NTOK; r += 256) s += rowloss[r];
    s = blockSum(s, red);
    if (threadIdx.x == 0) out[0] = s / (float)NTOK;
}

// ---------------- launch ----------------
extern "C" void kernel_launch(void* const* d_in, const int* in_sizes, int n_in,
                              void* d_out, int out_size) {
    const int*   x      = (const int*)d_in[0];
    const int*   target = (const int*)d_in[1];
    const float* tok    = (const float*)d_in[2];
    const float* pos    = (const float*)d_in[3];
    const float* Wq     = (const float*)d_in[4];
    const float* bq     = (const float*)d_in[5];
    const float* Wk     = (const float*)d_in[6];
    const float* bk     = (const float*)d_in[7];
    const float* Wv     = (const float*)d_in[8];
    const float* bv     = (const float*)d_in[9];
    const float* W_lm   = (const float*)d_in[10];
    const float* b_lm   = (const float*)d_in[11];
    float* out = (float*)d_out;

    const int SM3 = 3 * 4 * 16384;   // 196608 (3-pass, 3 stages)
    const int SM2 = 2 * 3 * 16384;   //  98304 (2-pass, 2 stages, 2 CTAs/SM)
    const int SM1 = 3 * 2 * 16384;   //  98304 (1-pass, 3 stages, 2 CTAs/SM)

    cudaFuncSetAttribute((const void*)mmagemm<0,2,1,false,2,2>, cudaFuncAttributeMaxDynamicSharedMemorySize, SM2);
    cudaFuncSetAttribute((const void*)mmagemm<0,2,2,false,2,2>, cudaFuncAttributeMaxDynamicSharedMemorySize, SM2);
    cudaFuncSetAttribute((const void*)mmagemm<0,2,0,false,2,2>, cudaFuncAttributeMaxDynamicSharedMemorySize, SM2);
    cudaFuncSetAttribute((const void*)mmagemm<1,2,0,false,2,2>, cudaFuncAttributeMaxDynamicSharedMemorySize, SM2);
    cudaFuncSetAttribute((const void*)mmagemm<2,3,1,false,3,1>, cudaFuncAttributeMaxDynamicSharedMemorySize, SM3);
    cudaFuncSetAttribute((const void*)mmagemm<0,1,0,true,3,2>,  cudaFuncAttributeMaxDynamicSharedMemorySize, SM1);

    __half *h_hi, *h_lo, *q_hi, *k_hi, *k_lo, *vT_hi, *vT_lo;
    __half *att_hi, *att_lo, *y_hi;
    __half *WqT_hi, *WqT_lo, *WkT_hi, *WkT_lo, *WvT_hi, *WvT_lo, *WlmT_hi;
    float *v, *att, *rowloss, *pm, *ps;
    cudaGetSymbolAddress((void**)&h_hi, g_h_hi);   cudaGetSymbolAddress((void**)&h_lo, g_h_lo);
    cudaGetSymbolAddress((void**)&q_hi, g_q_hi);
    cudaGetSymbolAddress((void**)&k_hi, g_k_hi);   cudaGetSymbolAddress((void**)&k_lo, g_k_lo);
    cudaGetSymbolAddress((void**)&v, g_v);
    cudaGetSymbolAddress((void**)&vT_hi, g_vT_hi); cudaGetSymbolAddress((void**)&vT_lo, g_vT_lo);
    cudaGetSymbolAddress((void**)&att, g_att);
    cudaGetSymbolAddress((void**)&att_hi, g_att_hi); cudaGetSymbolAddress((void**)&att_lo, g_att_lo);
    cudaGetSymbolAddress((void**)&y_hi, g_y_hi);
    cudaGetSymbolAddress((void**)&WqT_hi, g_WqT_hi); cudaGetSymbolAddress((void**)&WqT_lo, g_WqT_lo);
    cudaGetSymbolAddress((void**)&WkT_hi, g_WkT_hi); cudaGetSymbolAddress((void**)&WkT_lo, g_WkT_lo);
    cudaGetSymbolAddress((void**)&WvT_hi, g_WvT_hi); cudaGetSymbolAddress((void**)&WvT_lo, g_WvT_lo);
    cudaGetSymbolAddress((void**)&WlmT_hi, g_WlmT_hi);
    cudaGetSymbolAddress((void**)&pm, g_pm);       cudaGetSymbolAddress((void**)&ps, g_ps);
    cudaGetSymbolAddress((void**)&rowloss, g_rowloss);

    dim3 tb(32, 8);

    embed_split_kernel<<<(NTOK * DD + 255) / 256, 256>>>(x, tok, pos, h_hi, h_lo);

    // weight transposes: in [R=DD rows, C cols] -> out [C, DD]
    transpose_split_kernel<<<dim3(DD / 32, DD / 64, 1), tb>>>(Wq, WqT_hi, WqT_lo, DD, DD, 0, 0);
    transpose_split_kernel<<<dim3(DD / 32, DD / 64, 1), tb>>>(Wk, WkT_hi, WkT_lo, DD, DD, 0, 0);
    transpose_split_kernel<<<dim3(DD / 32, DD / 64, 1), tb>>>(Wv, WvT_hi, WvT_lo, DD, DD, 0, 0);
    transpose_split_kernel<<<dim3(VV / 32, DD / 64, 1), tb>>>(W_lm, WlmT_hi, nullptr, DD, VV, 0, 0);

    // q: 2-pass hi-out; k: 2-pass hi+lo out; v: 2-pass fp32-out (all 2 CTAs/SM)
    {
        dim3 grid((NTOK / BM) * (DD / 128), 1, 1);
        mmagemm<0,2,1,false,2,2><<<grid, GEMM_THREADS, SM2>>>(h_hi, nullptr, WqT_hi, WqT_lo, bq, 1.0f,
            nullptr, q_hi, nullptr, nullptr, nullptr, NTOK, DD, DD, 0, 0, 0);
        mmagemm<0,2,2,false,2,2><<<grid, GEMM_THREADS, SM2>>>(h_hi, nullptr, WkT_hi, WkT_lo, bk, 1.0f,
            nullptr, k_hi, k_lo, nullptr, nullptr, NTOK, DD, DD, 0, 0, 0);
        mmagemm<0,2,0,false,2,2><<<grid, GEMM_THREADS, SM2>>>(h_hi, nullptr, WvT_hi, WvT_lo, bv, 1.0f,
            v, nullptr, nullptr, nullptr, nullptr, NTOK, DD, DD, 0, 0, 0);
    }

    // v transpose per batch: [2048,1024] fp32 -> [1024,2048] fp16 hi/lo
    transpose_split_kernel<<<dim3(DD / 32, TT / 64, BB), tb>>>(v, vT_hi, vT_lo, TT, DD,
        (long long)TT * DD, (long long)TT * DD);

    // scores: 2-pass (A = q_hi; B = k hi+lo), lower-triangular tiles only
    {
        dim3 grid(136, 1, BB);
        mmagemm<1,2,0,false,2,2><<<grid, GEMM_THREADS, SM2>>>(q_hi, nullptr, k_hi, k_lo, nullptr, 0.03125f,
            att, nullptr, nullptr, nullptr, nullptr, TT, TT, DD,
            (long long)TT * DD, (long long)TT * DD, (long long)TT * TT);
    }

    softmax_split_kernel<<<NTOK, 256>>>(att, att_hi, att_lo);

    // y = attn @ v: 3-pass, K truncated, hi-only output
    {
        dim3 grid((TT / BM) * (DD / 128), 1, BB);
        mmagemm<2,3,1,false,3,1><<<grid, GEMM_THREADS, SM3>>>(att_hi, att_lo, vT_hi, vT_lo, nullptr, 1.0f,
            nullptr, y_hi, nullptr, nullptr, nullptr, TT, DD, TT,
            (long long)TT * TT, (long long)TT * DD, (long long)TT * DD);
    }

    // logits: 1-pass fp16, 2 CTAs/SM + fused loss partials
    {
        dim3 grid((NTOK / BM) * (VV / 128), 1, 1);
        mmagemm<0,1,0,true,3,2><<<grid, GEMM_THREADS, SM1>>>(y_hi, nullptr, WlmT_hi, nullptr, b_lm, 1.0f,
            out, nullptr, nullptr, pm, ps, NTOK, VV, DD, 0, 0, 0);
    }

    rowloss_partials_kernel<<<NTOK, 32>>>(pm, ps, out, target, rowloss);
    if ((long long)out_size > NLOGITS) {
        loss_reduce_kernel<<<1, 256>>>(rowloss, out + NLOGITS);
    }
}

// round 17
// speedup vs baseline: 1.1190x; 1.0172x over previous
#include <cuda_runtime.h>
#include <cuda_fp16.h>
#include <math.h>
#include <stdint.h>

// ---------------- problem dims ----------------
#define BB 4
#define TT 2048
#define DD 1024
#define VV 32000
#define NTOK (BB * TT)                 // 8192
#define NLOGITS 262144000LL
#define ATT_ELEMS ((long long)BB * TT * TT)
#define LM_NTILES (VV / 128)           // 250
#define NEG_SENT (-1e30f)

// ---------------- GEMM tiling ----------------
#define BM 128
#define BKC 64
#define GROUP_M 8
#define GEMM_THREADS 256

// ---------------- scratch ----------------
__device__ __half g_h_hi[NTOK * DD],  g_h_lo[NTOK * DD];
__device__ __half g_q_hi[NTOK * DD];
__device__ __half g_k_hi[NTOK * DD],  g_k_lo[NTOK * DD];
__device__ float  g_v[NTOK * DD];
__device__ __half g_vT_hi[NTOK * DD], g_vT_lo[NTOK * DD];
__device__ float  g_att[ATT_ELEMS];
__device__ __half g_att_hi[ATT_ELEMS];
__device__ __half g_y_hi[NTOK * DD];
__device__ __half g_WqT_hi[DD * DD],  g_WqT_lo[DD * DD];
__device__ __half g_WkT_hi[DD * DD],  g_WkT_lo[DD * DD];
__device__ __half g_WvT_hi[DD * DD],  g_WvT_lo[DD * DD];
__device__ __half g_WlmT_hi[(long long)VV * DD];
__device__ float  g_pm[(long long)NTOK * LM_NTILES];
__device__ float  g_ps[(long long)NTOK * LM_NTILES];
__device__ float  g_rowloss[NTOK];

// ---------------- helpers ----------------
__device__ __forceinline__ uint32_t smem_u32(const void* p) {
    uint32_t a;
    asm("{ .reg .u64 t; cvta.to.shared.u64 t, %1; cvt.u32.u64 %0, t; }" : "=r"(a) : "l"(p));
    return a;
}
__device__ __forceinline__ void cp16(uint32_t dst, const void* src) {
    asm volatile("cp.async.cg.shared.global [%0], [%1], 16;" :: "r"(dst), "l"(src));
}
__device__ __forceinline__ void ldsm_x4(uint32_t* r, uint32_t addr) {
    asm volatile("ldmatrix.sync.aligned.m8n8.x4.shared.b16 {%0,%1,%2,%3}, [%4];"
                 : "=r"(r[0]), "=r"(r[1]), "=r"(r[2]), "=r"(r[3]) : "r"(addr));
}
__device__ __forceinline__ void ldsm_x2(uint32_t* r, uint32_t addr) {
    asm volatile("ldmatrix.sync.aligned.m8n8.x2.shared.b16 {%0,%1}, [%2];"
                 : "=r"(r[0]), "=r"(r[1]) : "r"(addr));
}
__device__ __forceinline__ void mma_fp16(float* c, const uint32_t* a, const uint32_t* b) {
    asm volatile("mma.sync.aligned.m16n8k16.row.col.f32.f16.f16.f32 "
                 "{%0,%1,%2,%3}, {%4,%5,%6,%7}, {%8,%9}, {%0,%1,%2,%3};"
                 : "+f"(c[0]), "+f"(c[1]), "+f"(c[2]), "+f"(c[3])
                 : "r"(a[0]), "r"(a[1]), "r"(a[2]), "r"(a[3]), "r"(b[0]), "r"(b[1]));
}
__device__ __forceinline__ void split_h(float x, __half& hi, __half& lo) {
    hi = __float2half_rn(x);
    lo = __float2half_rn(x - __half2float(hi));
}

// ---------------- split-fp16 HMMA GEMM (BN=128) ----------------
// MODE 0: normal. MODE 1: lower-triangular tiles. MODE 2: K truncated at m0+BM.
// NPASS 3: hh + h*Blo + Alo*h.  NPASS 2: hh + h*Blo.  NPASS 1: hh.
// OUTM 0: f32. OUTM 1: fp16 hi. OUTM 2: fp16 hi+lo.
// FUSE: per-tile row (max, sumexp) partials. NSTG: stages. MINB: min blocks/SM.
template <int MODE, int NPASS, int OUTM, bool FUSE, int NSTG, int MINB>
__global__ void __launch_bounds__(GEMM_THREADS, MINB)
mmagemm(const __half* __restrict__ Ahi, const __half* __restrict__ Alo,
        const __half* __restrict__ Bhi, const __half* __restrict__ Blo,
        const float* __restrict__ bias, float alpha,
        float* __restrict__ C, __half* __restrict__ Chi, __half* __restrict__ Clo,
        float* __restrict__ pm, float* __restrict__ ps,
        int M, int N, int K,
        long long sA, long long sB, long long sC) {
    constexpr int NTILE = 16384;
    constexpr int T_AHI = 0;
    constexpr int T_ALO = (NPASS == 3) ? NTILE : 0;
    constexpr int T_BHI = ((NPASS == 3) ? 2 : 1) * NTILE;
    constexpr int T_BLO = T_BHI + NTILE;
    constexpr int STAGE = (((NPASS == 3) ? 2 : 1) + ((NPASS >= 2) ? 2 : 1)) * NTILE;

    extern __shared__ char smem[];
    const uint32_t sb = smem_u32(smem);
    const int tid = threadIdx.x;
    const int wid = tid >> 5, lane = tid & 31;
    const int wm = wid >> 2, wn = wid & 3;

    Ahi += blockIdx.z * sA;  if (NPASS == 3) Alo += blockIdx.z * sA;
    Bhi += blockIdx.z * sB;  if (NPASS >= 2) Blo += blockIdx.z * sB;
    if (OUTM == 0) C += blockIdx.z * sC;
    else { Chi += blockIdx.z * sC; if (OUTM == 2) Clo += blockIdx.z * sC; }

    int m0, n0;
    if (MODE == 1) {
        int idx = blockIdx.x;
        int row = (int)((sqrtf(8.0f * idx + 1.0f) - 1.0f) * 0.5f);
        while ((row + 1) * (row + 2) / 2 <= idx) ++row;
        while (row * (row + 1) / 2 > idx) --row;
        int col = idx - row * (row + 1) / 2;
        m0 = row * BM; n0 = col * 128;
    } else {
        const int npn = N / 128, npm = M / BM;
        int pid = blockIdx.x;
        int group = GROUP_M * npn;
        int gid = pid / group;
        int first = gid * GROUP_M;
        int gsz = min(GROUP_M, npm - first);
        m0 = (first + (pid % gsz)) * BM;
        n0 = ((pid % group) / gsz) * 128;
    }

    int NC = K / BKC;
    if (MODE == 2) NC = min(NC, (m0 + BM) / BKC);

    auto load_stage = [&](int chunk, int stage) {
        const uint32_t st = sb + stage * STAGE;
        const int kk = chunk * BKC;
#pragma unroll
        for (int it = 0; it < 4; it++) {
            int idx = tid + it * 256;
            int row = idx >> 3, ch = idx & 7;
            uint32_t dst = st + (uint32_t)(row * 128 + ((ch ^ (row & 7)) * 16));
            long long ga = (long long)(m0 + row) * K + kk + ch * 8;
            cp16(dst + T_AHI, Ahi + ga);
            if (NPASS == 3) cp16(dst + T_ALO, Alo + ga);
            long long gb = (long long)(n0 + row) * K + kk + ch * 8;
            cp16(dst + T_BHI, Bhi + gb);
            if (NPASS >= 2) cp16(dst + T_BLO, Blo + gb);
        }
        asm volatile("cp.async.commit_group;" ::: "memory");
    };

    float acc[4][4][4];
#pragma unroll
    for (int a = 0; a < 4; a++)
#pragma unroll
        for (int b = 0; b < 4; b++)
#pragma unroll
            for (int c = 0; c < 4; c++) acc[a][b][c] = 0.0f;

#pragma unroll
    for (int s = 0; s < NSTG - 1; s++)
        if (s < NC) load_stage(s, s);

    for (int i = 0; i < NC; i++) {
        if (i + NSTG - 2 < NC)
            asm volatile("cp.async.wait_group %0;" :: "n"(NSTG - 2) : "memory");
        else
            asm volatile("cp.async.wait_group 0;" ::: "memory");
        __syncthreads();
        if (i + NSTG - 1 < NC) load_stage(i + NSTG - 1, (i + NSTG - 1) % NSTG);

        const uint32_t st = sb + (i % NSTG) * STAGE;
#pragma unroll
        for (int ks = 0; ks < 4; ks++) {
            uint32_t ah[4][4], al[4][4], bh[4][2], bl[4][2];
#pragma unroll
            for (int mt = 0; mt < 4; mt++) {
                int row = wm * 64 + mt * 16 + (lane & 15);
                uint32_t off = (uint32_t)(row * 128 + ks * 32 + ((lane >> 4) * 16));
                off = off ^ ((off >> 3) & 0x70);
                ldsm_x4(ah[mt], st + T_AHI + off);
                if (NPASS == 3) ldsm_x4(al[mt], st + T_ALO + off);
            }
#pragma unroll
            for (int nt = 0; nt < 4; nt++) {
                int row = wn * 32 + nt * 8 + (lane & 7);
                uint32_t off = (uint32_t)(row * 128 + ks * 32 + (((lane >> 3) & 1) * 16));
                off = off ^ ((off >> 3) & 0x70);
                ldsm_x2(bh[nt], st + T_BHI + off);
                if (NPASS >= 2) ldsm_x2(bl[nt], st + T_BLO + off);
            }
#pragma unroll
            for (int mt = 0; mt < 4; mt++)
#pragma unroll
                for (int nt = 0; nt < 4; nt++) {
                    mma_fp16(acc[mt][nt], ah[mt], bh[nt]);
                    if (NPASS >= 2) mma_fp16(acc[mt][nt], ah[mt], bl[nt]);
                    if (NPASS == 3) mma_fp16(acc[mt][nt], al[mt], bh[nt]);
                }
        }
        __syncthreads();
    }

    const int tg = lane >> 2;
    const int tc = (lane & 3) * 2;
#pragma unroll
    for (int mt = 0; mt < 4; mt++)
#pragma unroll
        for (int nt = 0; nt < 4; nt++) {
            int c0 = n0 + wn * 32 + nt * 8 + tc;
            float b0 = bias ? bias[c0] : 0.0f;
            float b1 = bias ? bias[c0 + 1] : 0.0f;
            acc[mt][nt][0] = alpha * acc[mt][nt][0] + b0;
            acc[mt][nt][1] = alpha * acc[mt][nt][1] + b1;
            acc[mt][nt][2] = alpha * acc[mt][nt][2] + b0;
            acc[mt][nt][3] = alpha * acc[mt][nt][3] + b1;
        }

#pragma unroll
    for (int mt = 0; mt < 4; mt++)
#pragma unroll
        for (int nt = 0; nt < 4; nt++) {
            int r0 = m0 + wm * 64 + mt * 16 + tg;
            int c0 = n0 + wn * 32 + nt * 8 + tc;
            if (OUTM == 0) {
                *(float2*)(C + (long long)r0 * N + c0) = make_float2(acc[mt][nt][0], acc[mt][nt][1]);
                *(float2*)(C + (long long)(r0 + 8) * N + c0) = make_float2(acc[mt][nt][2], acc[mt][nt][3]);
            } else if (OUTM == 1) {
                *(__half2*)(Chi + (long long)r0 * N + c0) =
                    __half2(__float2half_rn(acc[mt][nt][0]), __float2half_rn(acc[mt][nt][1]));
                *(__half2*)(Chi + (long long)(r0 + 8) * N + c0) =
                    __half2(__float2half_rn(acc[mt][nt][2]), __float2half_rn(acc[mt][nt][3]));
            } else {
                __half h0, l0, h1, l1;
                split_h(acc[mt][nt][0], h0, l0); split_h(acc[mt][nt][1], h1, l1);
                *(__half2*)(Chi + (long long)r0 * N + c0) = __half2(h0, h1);
                *(__half2*)(Clo + (long long)r0 * N + c0) = __half2(l0, l1);
                split_h(acc[mt][nt][2], h0, l0); split_h(acc[mt][nt][3], h1, l1);
                *(__half2*)(Chi + (long long)(r0 + 8) * N + c0) = __half2(h0, h1);
                *(__half2*)(Clo + (long long)(r0 + 8) * N + c0) = __half2(l0, l1);
            }
        }

    if (FUSE) {
        float* smM = (float*)smem;
        float* smS = smM + 512;
        float rm[8], rs[8];
#pragma unroll
        for (int mt = 0; mt < 4; mt++)
#pragma unroll
            for (int hf = 0; hf < 2; hf++) {
                float m = NEG_SENT;
#pragma unroll
                for (int nt = 0; nt < 4; nt++) {
                    m = fmaxf(m, acc[mt][nt][hf * 2 + 0]);
                    m = fmaxf(m, acc[mt][nt][hf * 2 + 1]);
                }
                rm[mt * 2 + hf] = m;
            }
#pragma unroll
        for (int s = 0; s < 8; s++) {
            rm[s] = fmaxf(rm[s], __shfl_xor_sync(0xffffffffu, rm[s], 1));
            rm[s] = fmaxf(rm[s], __shfl_xor_sync(0xffffffffu, rm[s], 2));
        }
#pragma unroll
        for (int mt = 0; mt < 4; mt++)
#pragma unroll
            for (int hf = 0; hf < 2; hf++) {
                float m = rm[mt * 2 + hf], s = 0.0f;
#pragma unroll
                for (int nt = 0; nt < 4; nt++) {
                    s += __expf(acc[mt][nt][hf * 2 + 0] - m);
                    s += __expf(acc[mt][nt][hf * 2 + 1] - m);
                }
                rs[mt * 2 + hf] = s;
            }
#pragma unroll
        for (int s = 0; s < 8; s++) {
            rs[s] += __shfl_xor_sync(0xffffffffu, rs[s], 1);
            rs[s] += __shfl_xor_sync(0xffffffffu, rs[s], 2);
        }
        __syncthreads();
        if ((lane & 3) == 0) {
#pragma unroll
            for (int mt = 0; mt < 4; mt++)
#pragma unroll
                for (int hf = 0; hf < 2; hf++) {
                    int rin = wm * 64 + mt * 16 + hf * 8 + tg;
                    smM[wn * 128 + rin] = rm[mt * 2 + hf];
                    smS[wn * 128 + rin] = rs[mt * 2 + hf];
                }
        }
        __syncthreads();
        if (tid < 128) {
            float M4 = smM[tid];
            M4 = fmaxf(M4, smM[128 + tid]);
            M4 = fmaxf(M4, smM[256 + tid]);
            M4 = fmaxf(M4, smM[384 + tid]);
            float S4 = smS[tid] * __expf(smM[tid] - M4)
                     + smS[128 + tid] * __expf(smM[128 + tid] - M4)
                     + smS[256 + tid] * __expf(smM[256 + tid] - M4)
                     + smS[384 + tid] * __expf(smM[384 + tid] - M4);
            long long o = (long long)(m0 + tid) * (N / 128) + n0 / 128;
            pm[o] = M4; ps[o] = S4;
        }
    }
}

// ---------------- embedding (split fp16) ----------------
__global__ void embed_split_kernel(const int* __restrict__ x,
                                   const float* __restrict__ tok,
                                   const float* __restrict__ pos,
                                   __half* __restrict__ hhi, __half* __restrict__ hlo) {
    int i = blockIdx.x * blockDim.x + threadIdx.x;
    if (i >= NTOK * DD) return;
    int row = i >> 10;
    int d = i & 1023;
    int t = row & (TT - 1);
    float v = tok[(long long)x[row] * DD + d] + pos[t * DD + d];
    __half hi, lo;
    split_h(v, hi, lo);
    hhi[i] = hi; hlo[i] = lo;
}

// ---------------- transpose + split: 64(R) x 32(C) tiles, half2 stores ----------------
__global__ void __launch_bounds__(256)
transpose_split_kernel(const float* __restrict__ in,
                       __half* __restrict__ ohi, __half* __restrict__ olo,
                       int R, int C, long long sIn, long long sOut) {
    __shared__ float tbuf[64][33];
    in += blockIdx.z * sIn;
    ohi += blockIdx.z * sOut;
    if (olo) olo += blockIdx.z * sOut;
    int c0 = blockIdx.x * 32, r0 = blockIdx.y * 64;
    int tx = threadIdx.x, ty = threadIdx.y;
#pragma unroll
    for (int i = 0; i < 64; i += 8)
        tbuf[ty + i][tx] = in[(long long)(r0 + ty + i) * C + c0 + tx];
    __syncthreads();
#pragma unroll
    for (int i = 0; i < 32; i += 8) {
        int c = ty + i;
        float v0 = tbuf[2 * tx][c], v1 = tbuf[2 * tx + 1][c];
        long long o = (long long)(c0 + c) * R + r0 + 2 * tx;
        __half h0, l0, h1, l1;
        split_h(v0, h0, l0); split_h(v1, h1, l1);
        *(__half2*)(ohi + o) = __half2(h0, h1);
        if (olo) *(__half2*)(olo + o) = __half2(l0, l1);
    }
}

// ---------------- reductions ----------------
__device__ __forceinline__ float blockSum(float v, float* red) {
#pragma unroll
    for (int o = 16; o; o >>= 1) v += __shfl_xor_sync(0xffffffffu, v, o);
    if ((threadIdx.x & 31) == 0) red[threadIdx.x >> 5] = v;
    __syncthreads();
    float r = red[0];
#pragma unroll
    for (int i = 1; i < 8; i++) r += red[i];
    __syncthreads();
    return r;
}

// ---------------- causal softmax (online, 2 reads, finite sentinel) -> fp16 hi ----------------
__global__ void __launch_bounds__(256)
softmax_split_kernel(const float* __restrict__ att, __half* __restrict__ ahi) {
    __shared__ float redm[8], reds[8];
    int row = blockIdx.x;
    int i = row & (TT - 1);
    const float4* p4 = (const float4*)(att + (long long)row * TT);
    __half* ph = ahi + (long long)row * TT;
    int tid = threadIdx.x;
    int n4 = (i >> 2) + 1;

    // finite sentinel: avoids (-inf) - (-inf) = NaN in the combines below
    float m = NEG_SENT, s = 0.0f;
    for (int j = tid; j < n4; j += 256) {
        float4 v = p4[j];
        int b = j * 4;
        if (b + 1 > i) v.y = NEG_SENT;
        if (b + 2 > i) v.z = NEG_SENT;
        if (b + 3 > i) v.w = NEG_SENT;
        float cm = fmaxf(fmaxf(v.x, v.y), fmaxf(v.z, v.w));
        if (cm > m) { s *= __expf(m - cm); m = cm; }
        s += __expf(v.x - m) + __expf(v.y - m) + __expf(v.z - m) + __expf(v.w - m);
    }
#pragma unroll
    for (int o = 16; o; o >>= 1) {
        float om = __shfl_xor_sync(0xffffffffu, m, o);
        float os = __shfl_xor_sync(0xffffffffu, s, o);
        float nm = fmaxf(m, om);
        s = s * __expf(m - nm) + os * __expf(om - nm);
        m = nm;
    }
    if ((tid & 31) == 0) { redm[tid >> 5] = m; reds[tid >> 5] = s; }
    __syncthreads();
    float M = redm[0];
#pragma unroll
    for (int k = 1; k < 8; k++) M = fmaxf(M, redm[k]);
    float S = 0.0f;
#pragma unroll
    for (int k = 0; k < 8; k++) S += reds[k] * __expf(redm[k] - M);
    float inv = 1.0f / S;

    for (int j = tid; j < n4; j += 256) {
        float4 v = p4[j];
        int b = j * 4;
        if (b + 1 > i) v.y = NEG_SENT;
        if (b + 2 > i) v.z = NEG_SENT;
        if (b + 3 > i) v.w = NEG_SENT;
        float e0 = __expf(v.x - M) * inv, e1 = __expf(v.y - M) * inv;
        float e2 = __expf(v.z - M) * inv, e3 = __expf(v.w - M) * inv;
        ((__half2*)ph)[j * 2 + 0] = __half2(__float2half_rn(e0), __float2half_rn(e1));
        ((__half2*)ph)[j * 2 + 1] = __half2(__float2half_rn(e2), __float2half_rn(e3));
    }
    int jend4 = (((i >> 7) + 1) << 7) / 4;
    __half2 z2 = __half2(__float2half(0.0f), __float2half(0.0f));
    for (int j = n4 + tid; j < jend4; j += 256) {
        ((__half2*)ph)[j * 2 + 0] = z2;
        ((__half2*)ph)[j * 2 + 1] = z2;
    }
}

// ---------------- rowloss from fused partials ----------------
__global__ void __launch_bounds__(32)
rowloss_partials_kernel(const float* __restrict__ pm, const float* __restrict__ ps,
                        const float* __restrict__ logits, const int* __restrict__ target,
                        float* __restrict__ rowloss) {
    int row = blockIdx.x;
    int lane = threadIdx.x;
    float m = NEG_SENT, s = 0.0f;
    for (int t = lane; t < LM_NTILES; t += 32) {
        long long o = (long long)row * LM_NTILES + t;
        float tm = pm[o], ts = ps[o];
        float nm = fmaxf(m, tm);
        s = s * __expf(m - nm) + ts * __expf(tm - nm);
        m = nm;
    }
#pragma unroll
    for (int o = 16; o; o >>= 1) {
        float om = __shfl_xor_sync(0xffffffffu, m, o);
        float os = __shfl_xor_sync(0xffffffffu, s, o);
        float nm = fmaxf(m, om);
        s = s * __expf(m - nm) + os * __expf(om - nm);
        m = nm;
    }
    if (lane == 0)
        rowloss[row] = m + logf(s) - logits[(long long)row * VV + target[row]];
}

__global__ void __launch_bounds__(256)
loss_reduce_kernel(const float* __restrict__ rowloss, float* __restrict__ out) {
    __shared__ float red[8];
    float s = 0.0f;
    for (int r = threadIdx.x; r < NTOK; r += 256) s += rowloss[r];
    s = blockSum(s, red);
    if (threadIdx.x == 0) out[0] = s / (float)NTOK;
}

// ---------------- launch (single stream — capture/memory-guard safe) ----------------
extern "C" void kernel_launch(void* const* d_in, const int* in_sizes, int n_in,
                              void* d_out, int out_size) {
    const int*   x      = (const int*)d_in[0];
    const int*   target = (const int*)d_in[1];
    const float* tok    = (const float*)d_in[2];
    const float* pos    = (const float*)d_in[3];
    const float* Wq     = (const float*)d_in[4];
    const float* bq     = (const float*)d_in[5];
    const float* Wk     = (const float*)d_in[6];
    const float* bk     = (const float*)d_in[7];
    const float* Wv     = (const float*)d_in[8];
    const float* bv     = (const float*)d_in[9];
    const float* W_lm   = (const float*)d_in[10];
    const float* b_lm   = (const float*)d_in[11];
    float* out = (float*)d_out;

    const int SM2 = 2 * 3 * 16384;   //  98304 (2-pass, 2 stages, 2 CTAs/SM)
    const int SM1 = 3 * 2 * 16384;   //  98304 (1-pass, 3 stages, 2 CTAs/SM)

    cudaFuncSetAttribute((const void*)mmagemm<0,2,1,false,2,2>, cudaFuncAttributeMaxDynamicSharedMemorySize, SM2);
    cudaFuncSetAttribute((const void*)mmagemm<0,2,2,false,2,2>, cudaFuncAttributeMaxDynamicSharedMemorySize, SM2);
    cudaFuncSetAttribute((const void*)mmagemm<0,2,0,false,2,2>, cudaFuncAttributeMaxDynamicSharedMemorySize, SM2);
    cudaFuncSetAttribute((const void*)mmagemm<1,2,0,false,2,2>, cudaFuncAttributeMaxDynamicSharedMemorySize, SM2);
    cudaFuncSetAttribute((const void*)mmagemm<2,2,1,false,2,2>, cudaFuncAttributeMaxDynamicSharedMemorySize, SM2);
    cudaFuncSetAttribute((const void*)mmagemm<0,1,0,true,3,2>,  cudaFuncAttributeMaxDynamicSharedMemorySize, SM1);

    __half *h_hi, *h_lo, *q_hi, *k_hi, *k_lo, *vT_hi, *vT_lo;
    __half *att_hi, *y_hi;
    __half *WqT_hi, *WqT_lo, *WkT_hi, *WkT_lo, *WvT_hi, *WvT_lo, *WlmT_hi;
    float *v, *att, *rowloss, *pm, *ps;
    cudaGetSymbolAddress((void**)&h_hi, g_h_hi);   cudaGetSymbolAddress((void**)&h_lo, g_h_lo);
    cudaGetSymbolAddress((void**)&q_hi, g_q_hi);
    cudaGetSymbolAddress((void**)&k_hi, g_k_hi);   cudaGetSymbolAddress((void**)&k_lo, g_k_lo);
    cudaGetSymbolAddress((void**)&v, g_v);
    cudaGetSymbolAddress((void**)&vT_hi, g_vT_hi); cudaGetSymbolAddress((void**)&vT_lo, g_vT_lo);
    cudaGetSymbolAddress((void**)&att, g_att);
    cudaGetSymbolAddress((void**)&att_hi, g_att_hi);
    cudaGetSymbolAddress((void**)&y_hi, g_y_hi);
    cudaGetSymbolAddress((void**)&WqT_hi, g_WqT_hi); cudaGetSymbolAddress((void**)&WqT_lo, g_WqT_lo);
    cudaGetSymbolAddress((void**)&WkT_hi, g_WkT_hi); cudaGetSymbolAddress((void**)&WkT_lo, g_WkT_lo);
    cudaGetSymbolAddress((void**)&WvT_hi, g_WvT_hi); cudaGetSymbolAddress((void**)&WvT_lo, g_WvT_lo);
    cudaGetSymbolAddress((void**)&WlmT_hi, g_WlmT_hi);
    cudaGetSymbolAddress((void**)&pm, g_pm);       cudaGetSymbolAddress((void**)&ps, g_ps);
    cudaGetSymbolAddress((void**)&rowloss, g_rowloss);

    dim3 tb(32, 8);

    embed_split_kernel<<<(NTOK * DD + 255) / 256, 256>>>(x, tok, pos, h_hi, h_lo);

    transpose_split_kernel<<<dim3(DD / 32, DD / 64, 1), tb>>>(Wq, WqT_hi, WqT_lo, DD, DD, 0, 0);
    transpose_split_kernel<<<dim3(DD / 32, DD / 64, 1), tb>>>(Wk, WkT_hi, WkT_lo, DD, DD, 0, 0);
    transpose_split_kernel<<<dim3(DD / 32, DD / 64, 1), tb>>>(Wv, WvT_hi, WvT_lo, DD, DD, 0, 0);
    transpose_split_kernel<<<dim3(VV / 32, DD / 64, 1), tb>>>(W_lm, WlmT_hi, nullptr, DD, VV, 0, 0);

    // q: 2-pass hi-out; k: 2-pass hi+lo out; v: 2-pass fp32-out (2 CTAs/SM each)
    {
        dim3 grid((NTOK / BM) * (DD / 128), 1, 1);
        mmagemm<0,2,1,false,2,2><<<grid, GEMM_THREADS, SM2>>>(h_hi, nullptr, WqT_hi, WqT_lo, bq, 1.0f,
            nullptr, q_hi, nullptr, nullptr, nullptr, NTOK, DD, DD, 0, 0, 0);
        mmagemm<0,2,2,false,2,2><<<grid, GEMM_THREADS, SM2>>>(h_hi, nullptr, WkT_hi, WkT_lo, bk, 1.0f,
            nullptr, k_hi, k_lo, nullptr, nullptr, NTOK, DD, DD, 0, 0, 0);
        mmagemm<0,2,0,false,2,2><<<grid, GEMM_THREADS, SM2>>>(h_hi, nullptr, WvT_hi, WvT_lo, bv, 1.0f,
            v, nullptr, nullptr, nullptr, nullptr, NTOK, DD, DD, 0, 0, 0);
    }

    transpose_split_kernel<<<dim3(DD / 32, TT / 64, BB), tb>>>(v, vT_hi, vT_lo, TT, DD,
        (long long)TT * DD, (long long)TT * DD);

    // scores: 2-pass, lower-triangular tiles only
    {
        dim3 grid(136, 1, BB);
        mmagemm<1,2,0,false,2,2><<<grid, GEMM_THREADS, SM2>>>(q_hi, nullptr, k_hi, k_lo, nullptr, 0.03125f,
            att, nullptr, nullptr, nullptr, nullptr, TT, TT, DD,
            (long long)TT * DD, (long long)TT * DD, (long long)TT * TT);
    }

    softmax_split_kernel<<<NTOK, 256>>>(att, att_hi);

    // y = attn @ v: 2-pass (att_hi * (v_hi + v_lo)), K truncated, 2 CTAs/SM
    {
        dim3 grid((TT / BM) * (DD / 128), 1, BB);
        mmagemm<2,2,1,false,2,2><<<grid, GEMM_THREADS, SM2>>>(att_hi, nullptr, vT_hi, vT_lo, nullptr, 1.0f,
            nullptr, y_hi, nullptr, nullptr, nullptr, TT, DD, TT,
            (long long)TT * TT, (long long)TT * DD, (long long)TT * DD);
    }

    // logits: 1-pass fp16, fused loss partials
    {
        dim3 grid((NTOK / BM) * (VV / 128), 1, 1);
        mmagemm<0,1,0,true,3,2><<<grid, GEMM_THREADS, SM1>>>(y_hi, nullptr, WlmT_hi, nullptr, b_lm, 1.0f,
            out, nullptr, nullptr, pm, ps, NTOK, VV, DD, 0, 0, 0);
    }

    rowloss_partials_kernel<<<NTOK, 32>>>(pm, ps, out, target, rowloss);
    if ((long long)out_size > NLOGITS) {
        loss_reduce_kernel<<<1, 256>>>(rowloss, out + NLOGITS);
    }
}